// round 1
// baseline (speedup 1.0000x reference)
#include <cuda_runtime.h>
#include <math.h>

#define BDIM 128
#define NQ 384
#define NK 384
#define NH 8
#define CDIM 32
#define ADIM 256
#define ODIM 256
#define MROWS (BDIM*NQ)   // 49152

#define BM 128
#define BN 64
#define BK 16

// Scratch (allocation-free rule: __device__ globals)
__device__ float g_q[(size_t)BDIM*NH*NQ*CDIM];
__device__ float g_k[(size_t)BDIM*NH*NK*CDIM];
__device__ float g_v[(size_t)BDIM*NH*NK*CDIM];
__device__ float g_gate[(size_t)BDIM*NH*NQ*CDIM];
__device__ float g_wg[(size_t)BDIM*NQ*NH*CDIM];

// ---------------------------------------------------------------------------
// Shared SGEMM core: C[128x64] tile of A[MROWS,256] x W[256, >=nColBase+64]
// A row-major ld=256, W row-major ld=256. 256 threads, 8x4 micro-tile.
// ---------------------------------------------------------------------------
__device__ __forceinline__ void gemm_core(
    const float* __restrict__ A, const float* __restrict__ W,
    int rowBase, int nColBase, float acc[8][4])
{
    __shared__ float As[BK][BM + 1];
    __shared__ float Ws[BK][BN];
    const int t  = threadIdx.x;
    const int tx = t & 15;
    const int ty = t >> 4;

#pragma unroll
    for (int i = 0; i < 8; i++)
#pragma unroll
        for (int j = 0; j < 4; j++) acc[i][j] = 0.f;

    for (int k0 = 0; k0 < ADIM; k0 += BK) {
        // A tile: 128 rows x 16 k  (512 float4 slots, 2 per thread)
#pragma unroll
        for (int l = 0; l < 2; l++) {
            int s  = t + l * 256;
            int m  = s >> 2;
            int kk = (s & 3) << 2;
            float4 av = *(const float4*)(A + (size_t)(rowBase + m) * ADIM + k0 + kk);
            As[kk + 0][m] = av.x;
            As[kk + 1][m] = av.y;
            As[kk + 2][m] = av.z;
            As[kk + 3][m] = av.w;
        }
        // W tile: 16 k x 64 n (1 float4 per thread)
        {
            int k  = t >> 4;
            int n4 = (t & 15) << 2;
            float4 wv = *(const float4*)(W + (size_t)(k0 + k) * 256 + nColBase + n4);
            *(float4*)&Ws[k][n4] = wv;
        }
        __syncthreads();
#pragma unroll
        for (int k = 0; k < BK; k++) {
            float a[8], w[4];
#pragma unroll
            for (int i = 0; i < 8; i++) a[i] = As[k][ty * 8 + i];
#pragma unroll
            for (int j = 0; j < 4; j++) w[j] = Ws[k][tx * 4 + j];
#pragma unroll
            for (int i = 0; i < 8; i++)
#pragma unroll
                for (int j = 0; j < 4; j++)
                    acc[i][j] = fmaf(a[i], w[j], acc[i][j]);
        }
        __syncthreads();
    }
}

// q & gate projection: grid (8, 384). cols [0,256)=q (scaled), [256,512)=gate (sigmoid+bias)
__global__ __launch_bounds__(256) void proj_qg_kernel(
    const float* __restrict__ qdata, const float* __restrict__ query_w,
    const float* __restrict__ gating_w, const float* __restrict__ gating_b)
{
    const int rowBase = blockIdx.y * BM;
    const int n0 = blockIdx.x * BN;
    const bool isGate = (n0 >= 256);
    const float* W = isGate ? gating_w : query_w;
    const int nColBase = isGate ? (n0 - 256) : n0;

    float acc[8][4];
    gemm_core(qdata, W, rowBase, nColBase, acc);

    const float scale = 0.17677669529663687f; // 1/sqrt(32)
    const int t = threadIdx.x, tx = t & 15, ty = t >> 4;
#pragma unroll
    for (int i = 0; i < 8; i++) {
        int row = rowBase + ty * 8 + i;
        int b = row / NQ, qi = row % NQ;
#pragma unroll
        for (int j = 0; j < 4; j++) {
            int n = nColBase + tx * 4 + j;   // 0..255 within the matrix
            int h = n >> 5, c = n & 31;
            size_t idx = ((size_t)(b * NH + h) * NQ + qi) * CDIM + c;
            if (!isGate) {
                g_q[idx] = acc[i][j] * scale;
            } else {
                float x = acc[i][j] + gating_b[n];
                g_gate[idx] = 1.f / (1.f + __expf(-x));
            }
        }
    }
}

// k & v projection: grid (8, 384). cols [0,256)=k, [256,512)=v
__global__ __launch_bounds__(256) void proj_kv_kernel(
    const float* __restrict__ mdata, const float* __restrict__ key_w,
    const float* __restrict__ value_w)
{
    const int rowBase = blockIdx.y * BM;
    const int n0 = blockIdx.x * BN;
    const bool isV = (n0 >= 256);
    const float* W = isV ? value_w : key_w;
    const int nColBase = isV ? (n0 - 256) : n0;

    float acc[8][4];
    gemm_core(mdata, W, rowBase, nColBase, acc);

    const int t = threadIdx.x, tx = t & 15, ty = t >> 4;
#pragma unroll
    for (int i = 0; i < 8; i++) {
        int row = rowBase + ty * 8 + i;
        int b = row / NK, ki = row % NK;
#pragma unroll
        for (int j = 0; j < 4; j++) {
            int n = nColBase + tx * 4 + j;
            int h = n >> 5, c = n & 31;
            size_t idx = ((size_t)(b * NH + h) * NK + ki) * CDIM + c;
            if (!isV) g_k[idx] = acc[i][j];
            else      g_v[idx] = acc[i][j];
        }
    }
}

// fast exp(x) for x <= 0 (polynomial 2^f, keeps work on the FMA pipe, not MUFU)
__device__ __forceinline__ float fexp(float x)
{
    float t = fmaxf(x * 1.4426950408889634f, -126.f);
    float n = floorf(t);
    float f = t - n;
    // 2^f, f in [0,1): degree-6 Taylor of exp(f*ln2); max rel err ~1.5e-5
    float p = 1.5403530e-4f;
    p = fmaf(p, f, 1.3333558e-3f);
    p = fmaf(p, f, 9.6181291e-3f);
    p = fmaf(p, f, 5.5504109e-2f);
    p = fmaf(p, f, 2.4022651e-1f);
    p = fmaf(p, f, 6.9314718e-1f);
    p = fmaf(p, f, 1.0f);
    float s = __int_as_float(((int)n + 127) << 23);
    return p * s;
}

// Attention: one block per (b,h); 384 threads, one q-row per thread.
// K/V staged in 96KB dynamic SMEM; online softmax; gate applied in epilogue.
__global__ __launch_bounds__(384) void attn_kernel(
    const float* __restrict__ bias, const float* __restrict__ nb)
{
    const int bh = blockIdx.x;
    const int b = bh >> 3, h = bh & 7;
    extern __shared__ float sh[];
    float* ksh = sh;                 // [384][32]
    float* vsh = sh + NK * CDIM;     // [384][32]

    const float4* kg = (const float4*)(g_k + (size_t)bh * NK * CDIM);
    const float4* vg = (const float4*)(g_v + (size_t)bh * NK * CDIM);
    const int tid = threadIdx.x;
    for (int s = tid; s < NK * CDIM / 4; s += 384) {
        ((float4*)ksh)[s] = kg[s];
        ((float4*)vsh)[s] = vg[s];
    }
    __syncthreads();

    const int i = tid; // q row
    float q[32];
    const float4* qrow = (const float4*)(g_q + ((size_t)bh * NQ + i) * CDIM);
#pragma unroll
    for (int c8 = 0; c8 < 8; c8++) {
        float4 v4 = qrow[c8];
        q[c8 * 4 + 0] = v4.x; q[c8 * 4 + 1] = v4.y;
        q[c8 * 4 + 2] = v4.z; q[c8 * 4 + 3] = v4.w;
    }
    const float* brow = bias + ((size_t)b * NQ + i) * NK;
    const float* nrow = nb + (size_t)i * NK;

    float m = -1e30f, sum = 0.f;
    float acc[32];
#pragma unroll
    for (int c = 0; c < 32; c++) acc[c] = 0.f;

    for (int j = 0; j < NK; j++) {
        const float4* kj = (const float4*)(ksh + j * CDIM);
        float s0 = 0.f, s1 = 0.f, s2 = 0.f, s3 = 0.f;
#pragma unroll
        for (int c8 = 0; c8 < 8; c8++) {
            float4 kv = kj[c8];
            s0 = fmaf(q[c8 * 4 + 0], kv.x, s0);
            s1 = fmaf(q[c8 * 4 + 1], kv.y, s1);
            s2 = fmaf(q[c8 * 4 + 2], kv.z, s2);
            s3 = fmaf(q[c8 * 4 + 3], kv.w, s3);
        }
        float sc = (s0 + s1) + (s2 + s3) + brow[j] + nrow[j];
        float p;
        if (sc > m) {
            float corr = fexp(m - sc);
            sum *= corr;
#pragma unroll
            for (int c = 0; c < 32; c++) acc[c] *= corr;
            m = sc;
            p = 1.f;
        } else {
            p = fexp(sc - m);
        }
        sum += p;
        const float4* vj = (const float4*)(vsh + j * CDIM);
#pragma unroll
        for (int c8 = 0; c8 < 8; c8++) {
            float4 vv = vj[c8];
            acc[c8 * 4 + 0] = fmaf(p, vv.x, acc[c8 * 4 + 0]);
            acc[c8 * 4 + 1] = fmaf(p, vv.y, acc[c8 * 4 + 1]);
            acc[c8 * 4 + 2] = fmaf(p, vv.z, acc[c8 * 4 + 2]);
            acc[c8 * 4 + 3] = fmaf(p, vv.w, acc[c8 * 4 + 3]);
        }
    }

    float inv = 1.f / sum;
    const float4* grow = (const float4*)(g_gate + ((size_t)bh * NQ + i) * CDIM);
    float4* wrow = (float4*)(g_wg + (((size_t)b * NQ + i) * NH + h) * CDIM);
#pragma unroll
    for (int c8 = 0; c8 < 8; c8++) {
        float4 gv = grow[c8];
        float4 o;
        o.x = acc[c8 * 4 + 0] * inv * gv.x;
        o.y = acc[c8 * 4 + 1] * inv * gv.y;
        o.z = acc[c8 * 4 + 2] * inv * gv.z;
        o.w = acc[c8 * 4 + 3] * inv * gv.w;
        wrow[c8] = o;
    }
}

// Output projection: wg[49152,256] x output_w[256,256] + output_b. grid (4,384)
__global__ __launch_bounds__(256) void out_kernel(
    const float* __restrict__ output_w, const float* __restrict__ output_b,
    float* __restrict__ out)
{
    const int rowBase = blockIdx.y * BM;
    const int n0 = blockIdx.x * BN;
    float acc[8][4];
    gemm_core(g_wg, output_w, rowBase, n0, acc);

    const int t = threadIdx.x, tx = t & 15, ty = t >> 4;
#pragma unroll
    for (int i = 0; i < 8; i++) {
        int row = rowBase + ty * 8 + i;
#pragma unroll
        for (int j = 0; j < 4; j++) {
            int n = n0 + tx * 4 + j;
            out[(size_t)row * ODIM + n] = acc[i][j] + output_b[n];
        }
    }
}

extern "C" void kernel_launch(void* const* d_in, const int* in_sizes, int n_in,
                              void* d_out, int out_size)
{
    const float* q_data   = (const float*)d_in[0];
    const float* m_data   = (const float*)d_in[1];
    const float* bias     = (const float*)d_in[2];
    const float* nbias    = (const float*)d_in[3];
    const float* query_w  = (const float*)d_in[4];
    const float* key_w    = (const float*)d_in[5];
    const float* value_w  = (const float*)d_in[6];
    const float* gating_w = (const float*)d_in[7];
    const float* gating_b = (const float*)d_in[8];
    const float* output_w = (const float*)d_in[9];
    const float* output_b = (const float*)d_in[10];
    float* out = (float*)d_out;

    const int smem_attn = 2 * NK * CDIM * (int)sizeof(float); // 96 KB
    cudaFuncSetAttribute(attn_kernel, cudaFuncAttributeMaxDynamicSharedMemorySize, smem_attn);

    dim3 gproj(8, MROWS / BM);
    proj_qg_kernel<<<gproj, 256>>>(q_data, query_w, gating_w, gating_b);
    proj_kv_kernel<<<gproj, 256>>>(m_data, key_w, value_w);
    attn_kernel<<<BDIM * NH, 384, smem_attn>>>(bias, nbias);
    dim3 gout(4, MROWS / BM);
    out_kernel<<<gout, 256>>>(output_w, output_b, out);
}

// round 2
// speedup vs baseline: 1.4153x; 1.4153x over previous
#include <cuda_runtime.h>
#include <math.h>

#define BDIM 128
#define NQ 384
#define NK 384
#define NH 8
#define CDIM 32
#define ADIM 256
#define ODIM 256
#define MROWS (BDIM*NQ)   // 49152

#define BM 128
#define BN 64
#define BK 16

#define JT 32           // attention j-tile
#define BPAD 385        // padded q-stride of bias tile in smem

// Scratch (allocation-free rule: __device__ globals)
__device__ float g_q[(size_t)BDIM*NH*NQ*CDIM];
__device__ float g_k[(size_t)BDIM*NH*NK*CDIM];
__device__ float g_v[(size_t)BDIM*NH*NK*CDIM];
__device__ float g_gate[(size_t)BDIM*NH*NQ*CDIM];
__device__ float g_wg[(size_t)BDIM*NQ*NH*CDIM];
__device__ float g_bias2[(size_t)BDIM*NQ*NK];

// ---------------------------------------------------------------------------
// Shared SGEMM core: C[128x64] tile of A[MROWS,256] x W[256, >=nColBase+64]
// ---------------------------------------------------------------------------
__device__ __forceinline__ void gemm_core(
    const float* __restrict__ A, const float* __restrict__ W,
    int rowBase, int nColBase, float acc[8][4])
{
    __shared__ float As[BK][BM + 1];
    __shared__ float Ws[BK][BN];
    const int t  = threadIdx.x;
    const int tx = t & 15;
    const int ty = t >> 4;

#pragma unroll
    for (int i = 0; i < 8; i++)
#pragma unroll
        for (int j = 0; j < 4; j++) acc[i][j] = 0.f;

    for (int k0 = 0; k0 < ADIM; k0 += BK) {
#pragma unroll
        for (int l = 0; l < 2; l++) {
            int s  = t + l * 256;
            int m  = s >> 2;
            int kk = (s & 3) << 2;
            float4 av = *(const float4*)(A + (size_t)(rowBase + m) * ADIM + k0 + kk);
            As[kk + 0][m] = av.x;
            As[kk + 1][m] = av.y;
            As[kk + 2][m] = av.z;
            As[kk + 3][m] = av.w;
        }
        {
            int k  = t >> 4;
            int n4 = (t & 15) << 2;
            float4 wv = *(const float4*)(W + (size_t)(k0 + k) * 256 + nColBase + n4);
            *(float4*)&Ws[k][n4] = wv;
        }
        __syncthreads();
#pragma unroll
        for (int k = 0; k < BK; k++) {
            float a[8], w[4];
#pragma unroll
            for (int i = 0; i < 8; i++) a[i] = As[k][ty * 8 + i];
#pragma unroll
            for (int j = 0; j < 4; j++) w[j] = Ws[k][tx * 4 + j];
#pragma unroll
            for (int i = 0; i < 8; i++)
#pragma unroll
                for (int j = 0; j < 4; j++)
                    acc[i][j] = fmaf(a[i], w[j], acc[i][j]);
        }
        __syncthreads();
    }
}

// q & gate projection: grid (8, 384). cols [0,256)=q (scaled), [256,512)=gate
__global__ __launch_bounds__(256) void proj_qg_kernel(
    const float* __restrict__ qdata, const float* __restrict__ query_w,
    const float* __restrict__ gating_w, const float* __restrict__ gating_b)
{
    const int rowBase = blockIdx.y * BM;
    const int n0 = blockIdx.x * BN;
    const bool isGate = (n0 >= 256);
    const float* W = isGate ? gating_w : query_w;
    const int nColBase = isGate ? (n0 - 256) : n0;

    float acc[8][4];
    gemm_core(qdata, W, rowBase, nColBase, acc);

    const float scale = 0.17677669529663687f; // 1/sqrt(32)
    const int t = threadIdx.x, tx = t & 15, ty = t >> 4;
#pragma unroll
    for (int i = 0; i < 8; i++) {
        int row = rowBase + ty * 8 + i;
        int b = row / NQ, qi = row % NQ;
#pragma unroll
        for (int j = 0; j < 4; j++) {
            int n = nColBase + tx * 4 + j;
            int h = n >> 5, c = n & 31;
            size_t idx = ((size_t)(b * NH + h) * NQ + qi) * CDIM + c;
            if (!isGate) {
                g_q[idx] = acc[i][j] * scale;
            } else {
                float x = acc[i][j] + gating_b[n];
                g_gate[idx] = 1.f / (1.f + __expf(-x));
            }
        }
    }
}

// k & v projection: grid (8, 384). cols [0,256)=k, [256,512)=v
__global__ __launch_bounds__(256) void proj_kv_kernel(
    const float* __restrict__ mdata, const float* __restrict__ key_w,
    const float* __restrict__ value_w)
{
    const int rowBase = blockIdx.y * BM;
    const int n0 = blockIdx.x * BN;
    const bool isV = (n0 >= 256);
    const float* W = isV ? value_w : key_w;
    const int nColBase = isV ? (n0 - 256) : n0;

    float acc[8][4];
    gemm_core(mdata, W, rowBase, nColBase, acc);

    const int t = threadIdx.x, tx = t & 15, ty = t >> 4;
#pragma unroll
    for (int i = 0; i < 8; i++) {
        int row = rowBase + ty * 8 + i;
        int b = row / NK, ki = row % NK;
#pragma unroll
        for (int j = 0; j < 4; j++) {
            int n = nColBase + tx * 4 + j;
            int h = n >> 5, c = n & 31;
            size_t idx = ((size_t)(b * NH + h) * NK + ki) * CDIM + c;
            if (!isV) g_k[idx] = acc[i][j];
            else      g_v[idx] = acc[i][j];
        }
    }
}

// bias2 = bias + broadcast(nonbatched_bias)   (float4 vectorized)
__global__ __launch_bounds__(256) void bias_add_kernel(
    const float* __restrict__ bias, const float* __restrict__ nb)
{
    size_t s = (size_t)blockIdx.x * blockDim.x + threadIdx.x;  // float4 index
    const size_t n4 = (size_t)BDIM * NQ * NK / 4;
    if (s >= n4) return;
    const size_t per_b4 = (size_t)NQ * NK / 4;
    size_t rem = s % per_b4;
    float4 bv = ((const float4*)bias)[s];
    float4 nv = ((const float4*)nb)[rem];
    bv.x += nv.x; bv.y += nv.y; bv.z += nv.z; bv.w += nv.w;
    ((float4*)g_bias2)[s] = bv;
}

// fast exp(x) for x <= 0 (polynomial 2^f on the FMA pipe)
__device__ __forceinline__ float fexp(float x)
{
    float t = fmaxf(x * 1.4426950408889634f, -126.f);
    float n = floorf(t);
    float f = t - n;
    float p = 1.5403530e-4f;
    p = fmaf(p, f, 1.3333558e-3f);
    p = fmaf(p, f, 9.6181291e-3f);
    p = fmaf(p, f, 5.5504109e-2f);
    p = fmaf(p, f, 2.4022651e-1f);
    p = fmaf(p, f, 6.9314718e-1f);
    p = fmaf(p, f, 1.0f);
    float s = __int_as_float(((int)n + 127) << 23);
    return p * s;
}

// Attention: one block per (b,h); 384 threads, one q-row per thread.
// K/V staged in SMEM; bias staged per 32-wide j-tile (coalesced, transposed).
__global__ __launch_bounds__(384) void attn_kernel()
{
    const int bh = blockIdx.x;
    const int b = bh >> 3, h = bh & 7;
    extern __shared__ float sh[];
    float* ksh = sh;                         // [384][32]
    float* vsh = sh + NK * CDIM;             // [384][32]
    float* bsh = sh + 2 * NK * CDIM;         // [JT][BPAD]  (j-major, padded)

    const float4* kg = (const float4*)(g_k + (size_t)bh * NK * CDIM);
    const float4* vg = (const float4*)(g_v + (size_t)bh * NK * CDIM);
    const int tid = threadIdx.x;
    for (int s = tid; s < NK * CDIM / 4; s += 384) {
        ((float4*)ksh)[s] = kg[s];
        ((float4*)vsh)[s] = vg[s];
    }

    const int i = tid; // q row
    float q[32];
    const float4* qrow = (const float4*)(g_q + ((size_t)bh * NQ + i) * CDIM);
#pragma unroll
    for (int c8 = 0; c8 < 8; c8++) {
        float4 v4 = qrow[c8];
        q[c8 * 4 + 0] = v4.x; q[c8 * 4 + 1] = v4.y;
        q[c8 * 4 + 2] = v4.z; q[c8 * 4 + 3] = v4.w;
    }

    const float* bias2 = g_bias2 + (size_t)b * NQ * NK;

    float m = -1e30f, sum = 0.f;
    float acc[32];
#pragma unroll
    for (int c = 0; c < 32; c++) acc[c] = 0.f;

    for (int jt = 0; jt < NK; jt += JT) {
        __syncthreads();   // previous bias tile fully consumed (also covers K/V staging on iter 0)
        // Stage bias tile: [384 q][32 j] from gmem -> bsh[jj][q] transposed.
        // 3072 float4 total, 8 per thread; lanes read 16B-consecutive chunks.
#pragma unroll
        for (int l = 0; l < 8; l++) {
            int s   = tid + l * 384;
            int r   = s >> 3;            // q row 0..383
            int seg = s & 7;             // 4-j segment
            float4 bv = *(const float4*)(bias2 + (size_t)r * NK + jt + seg * 4);
            bsh[(seg * 4 + 0) * BPAD + r] = bv.x;
            bsh[(seg * 4 + 1) * BPAD + r] = bv.y;
            bsh[(seg * 4 + 2) * BPAD + r] = bv.z;
            bsh[(seg * 4 + 3) * BPAD + r] = bv.w;
        }
        __syncthreads();

#pragma unroll 4
        for (int jj = 0; jj < JT; jj++) {
            const int j = jt + jj;
            const float4* kj = (const float4*)(ksh + j * CDIM);
            float s0 = 0.f, s1 = 0.f, s2 = 0.f, s3 = 0.f;
#pragma unroll
            for (int c8 = 0; c8 < 8; c8++) {
                float4 kv = kj[c8];
                s0 = fmaf(q[c8 * 4 + 0], kv.x, s0);
                s1 = fmaf(q[c8 * 4 + 1], kv.y, s1);
                s2 = fmaf(q[c8 * 4 + 2], kv.z, s2);
                s3 = fmaf(q[c8 * 4 + 3], kv.w, s3);
            }
            float sc = (s0 + s1) + (s2 + s3) + bsh[jj * BPAD + i];
            float p;
            if (sc > m) {
                float corr = fexp(m - sc);
                sum *= corr;
#pragma unroll
                for (int c = 0; c < 32; c++) acc[c] *= corr;
                m = sc;
                p = 1.f;
            } else {
                p = fexp(sc - m);
            }
            sum += p;
            const float4* vj = (const float4*)(vsh + j * CDIM);
#pragma unroll
            for (int c8 = 0; c8 < 8; c8++) {
                float4 vv = vj[c8];
                acc[c8 * 4 + 0] = fmaf(p, vv.x, acc[c8 * 4 + 0]);
                acc[c8 * 4 + 1] = fmaf(p, vv.y, acc[c8 * 4 + 1]);
                acc[c8 * 4 + 2] = fmaf(p, vv.z, acc[c8 * 4 + 2]);
                acc[c8 * 4 + 3] = fmaf(p, vv.w, acc[c8 * 4 + 3]);
            }
        }
    }

    float inv = 1.f / sum;
    const float4* grow = (const float4*)(g_gate + ((size_t)bh * NQ + i) * CDIM);
    float4* wrow = (float4*)(g_wg + (((size_t)b * NQ + i) * NH + h) * CDIM);
#pragma unroll
    for (int c8 = 0; c8 < 8; c8++) {
        float4 gv = grow[c8];
        float4 o;
        o.x = acc[c8 * 4 + 0] * inv * gv.x;
        o.y = acc[c8 * 4 + 1] * inv * gv.y;
        o.z = acc[c8 * 4 + 2] * inv * gv.z;
        o.w = acc[c8 * 4 + 3] * inv * gv.w;
        wrow[c8] = o;
    }
}

// Output projection: wg[49152,256] x output_w[256,256] + output_b. grid (4,384)
__global__ __launch_bounds__(256) void out_kernel(
    const float* __restrict__ output_w, const float* __restrict__ output_b,
    float* __restrict__ out)
{
    const int rowBase = blockIdx.y * BM;
    const int n0 = blockIdx.x * BN;
    float acc[8][4];
    gemm_core(g_wg, output_w, rowBase, n0, acc);

    const int t = threadIdx.x, tx = t & 15, ty = t >> 4;
#pragma unroll
    for (int i = 0; i < 8; i++) {
        int row = rowBase + ty * 8 + i;
#pragma unroll
        for (int j = 0; j < 4; j++) {
            int n = n0 + tx * 4 + j;
            out[(size_t)row * ODIM + n] = acc[i][j] + output_b[n];
        }
    }
}

extern "C" void kernel_launch(void* const* d_in, const int* in_sizes, int n_in,
                              void* d_out, int out_size)
{
    const float* q_data   = (const float*)d_in[0];
    const float* m_data   = (const float*)d_in[1];
    const float* bias     = (const float*)d_in[2];
    const float* nbias    = (const float*)d_in[3];
    const float* query_w  = (const float*)d_in[4];
    const float* key_w    = (const float*)d_in[5];
    const float* value_w  = (const float*)d_in[6];
    const float* gating_w = (const float*)d_in[7];
    const float* gating_b = (const float*)d_in[8];
    const float* output_w = (const float*)d_in[9];
    const float* output_b = (const float*)d_in[10];
    float* out = (float*)d_out;

    const int smem_attn = (2 * NK * CDIM + JT * BPAD) * (int)sizeof(float); // ~147.5 KB
    static int s_attr_set = 0;
    cudaFuncSetAttribute(attn_kernel, cudaFuncAttributeMaxDynamicSharedMemorySize, smem_attn);
    (void)s_attr_set;

    dim3 gproj(8, MROWS / BM);
    proj_qg_kernel<<<gproj, 256>>>(q_data, query_w, gating_w, gating_b);
    proj_kv_kernel<<<gproj, 256>>>(m_data, key_w, value_w);
    {
        size_t n4 = (size_t)BDIM * NQ * NK / 4;
        int blocks = (int)((n4 + 255) / 256);
        bias_add_kernel<<<blocks, 256>>>(bias, nbias);
    }
    attn_kernel<<<BDIM * NH, 384, smem_attn>>>();
    dim3 gout(4, MROWS / BM);
    out_kernel<<<gout, 256>>>(output_w, output_b, out);
}

// round 3
// speedup vs baseline: 1.8551x; 1.3107x over previous
#include <cuda_runtime.h>
#include <math.h>

#define BDIM 128
#define NQ 384
#define NK 384
#define NH 8
#define CDIM 32
#define ADIM 256
#define ODIM 256
#define MROWS (BDIM*NQ)   // 49152

#define BM 128
#define BN 64
#define BK 16
#define ASTRIDE 20        // As[m][k] padded k-stride (conflict-free frag loads)
#define WSTRIDE 72        // Ws[k][n] padded n-stride

#define JT 32             // attention j-tile
#define BPAD 385          // padded q-stride of bias tile in smem

// Scratch (allocation-free rule: __device__ globals)
__device__ float g_q[(size_t)BDIM*NH*NQ*CDIM];
__device__ float g_k[(size_t)BDIM*NH*NK*CDIM];
__device__ float g_v[(size_t)BDIM*NH*NK*CDIM];
__device__ float g_gate[(size_t)BDIM*NH*NQ*CDIM];
__device__ float g_wg[(size_t)BDIM*NQ*NH*CDIM];
__device__ float g_bias2[(size_t)BDIM*NQ*NK];

// ---------------------------------------------------------------------------
// tf32 helpers
// ---------------------------------------------------------------------------
__device__ __forceinline__ float to_tf32(float x)
{
    float r;
    asm("cvt.rna.tf32.f32 %0, %1;" : "=f"(r) : "f"(x));
    return r;
}

__device__ __forceinline__ void mma_tf32(float d[4], const unsigned a[4], const unsigned b[2])
{
    asm volatile(
        "mma.sync.aligned.m16n8k8.row.col.f32.tf32.tf32.f32 "
        "{%0,%1,%2,%3}, {%4,%5,%6,%7}, {%8,%9}, {%0,%1,%2,%3};"
        : "+f"(d[0]), "+f"(d[1]), "+f"(d[2]), "+f"(d[3])
        : "r"(a[0]), "r"(a[1]), "r"(a[2]), "r"(a[3]),
          "r"(b[0]), "r"(b[1]));
}

// ---------------------------------------------------------------------------
// tf32 MMA GEMM core: C[128x64] tile of A[MROWS,256] x W[256, nColBase+64]
// 256 threads = 8 warps; warp tile 32x32 (2 m16 x 4 n8 frags, K in steps of 8).
// acc[mf][nf][r]: r-> c-frag layout (c0:(g,2t) c1:(g,2t+1) c2:(g+8,2t) c3:(g+8,2t+1))
// ---------------------------------------------------------------------------
__device__ __forceinline__ void gemm_core_mma(
    const float* __restrict__ A, const float* __restrict__ W,
    int rowBase, int nColBase, float acc[2][4][4])
{
    __shared__ float As[BM][ASTRIDE];
    __shared__ float Ws[BK][WSTRIDE];
    const int t    = threadIdx.x;
    const int lane = t & 31;
    const int wid  = t >> 5;
    const int g    = lane >> 2;
    const int tg   = lane & 3;
    const int mBase = (wid & 3) * 32;
    const int nBase = (wid >> 2) * 32;

#pragma unroll
    for (int mf = 0; mf < 2; mf++)
#pragma unroll
        for (int nf = 0; nf < 4; nf++)
#pragma unroll
            for (int r = 0; r < 4; r++) acc[mf][nf][r] = 0.f;

    for (int k0 = 0; k0 < ADIM; k0 += BK) {
        // A tile: 128 rows x 16 k  (2 float4 per thread), tf32-converted
#pragma unroll
        for (int l = 0; l < 2; l++) {
            int s  = t + l * 256;
            int m  = s >> 2;
            int kk = (s & 3) << 2;
            float4 av = *(const float4*)(A + (size_t)(rowBase + m) * ADIM + k0 + kk);
            As[m][kk + 0] = to_tf32(av.x);
            As[m][kk + 1] = to_tf32(av.y);
            As[m][kk + 2] = to_tf32(av.z);
            As[m][kk + 3] = to_tf32(av.w);
        }
        // W tile: 16 k x 64 n (1 float4 per thread), tf32-converted
        {
            int k  = t >> 4;
            int n4 = (t & 15) << 2;
            float4 wv = *(const float4*)(W + (size_t)(k0 + k) * 256 + nColBase + n4);
            Ws[k][n4 + 0] = to_tf32(wv.x);
            Ws[k][n4 + 1] = to_tf32(wv.y);
            Ws[k][n4 + 2] = to_tf32(wv.z);
            Ws[k][n4 + 3] = to_tf32(wv.w);
        }
        __syncthreads();

#pragma unroll
        for (int ks = 0; ks < BK; ks += 8) {
            unsigned a[2][4], b[4][2];
#pragma unroll
            for (int mf = 0; mf < 2; mf++) {
                int m0 = mBase + mf * 16 + g;
                a[mf][0] = __float_as_uint(As[m0    ][ks + tg    ]);
                a[mf][1] = __float_as_uint(As[m0 + 8][ks + tg    ]);
                a[mf][2] = __float_as_uint(As[m0    ][ks + tg + 4]);
                a[mf][3] = __float_as_uint(As[m0 + 8][ks + tg + 4]);
            }
#pragma unroll
            for (int nf = 0; nf < 4; nf++) {
                int n0 = nBase + nf * 8 + g;
                b[nf][0] = __float_as_uint(Ws[ks + tg    ][n0]);
                b[nf][1] = __float_as_uint(Ws[ks + tg + 4][n0]);
            }
#pragma unroll
            for (int mf = 0; mf < 2; mf++)
#pragma unroll
                for (int nf = 0; nf < 4; nf++)
                    mma_tf32(acc[mf][nf], a[mf], b[nf]);
        }
        __syncthreads();
    }
}

// q & gate projection: grid (8, 384). cols [0,256)=q (scaled), [256,512)=gate
__global__ __launch_bounds__(256) void proj_qg_kernel(
    const float* __restrict__ qdata, const float* __restrict__ query_w,
    const float* __restrict__ gating_w, const float* __restrict__ gating_b)
{
    const int rowBase = blockIdx.y * BM;
    const int n0 = blockIdx.x * BN;
    const bool isGate = (n0 >= 256);
    const float* W = isGate ? gating_w : query_w;
    const int nColBase = isGate ? (n0 - 256) : n0;

    float acc[2][4][4];
    gemm_core_mma(qdata, W, rowBase, nColBase, acc);

    const float scale = 0.17677669529663687f; // 1/sqrt(32)
    const int t = threadIdx.x, lane = t & 31, wid = t >> 5;
    const int g = lane >> 2, tg = lane & 3;
    const int mBase = (wid & 3) * 32, nBase = (wid >> 2) * 32;
#pragma unroll
    for (int mf = 0; mf < 2; mf++)
#pragma unroll
        for (int nf = 0; nf < 4; nf++)
#pragma unroll
            for (int r = 0; r < 4; r++) {
                int row = rowBase + mBase + mf * 16 + ((r & 2) ? 8 : 0) + g;
                int n   = nColBase + nBase + nf * 8 + tg * 2 + (r & 1);
                int b = row / NQ, qi = row % NQ;
                int h = n >> 5, c = n & 31;
                size_t idx = ((size_t)(b * NH + h) * NQ + qi) * CDIM + c;
                if (!isGate) {
                    g_q[idx] = acc[mf][nf][r] * scale;
                } else {
                    float x = acc[mf][nf][r] + gating_b[n];
                    g_gate[idx] = 1.f / (1.f + __expf(-x));
                }
            }
}

// k & v projection: grid (8, 384). cols [0,256)=k, [256,512)=v
__global__ __launch_bounds__(256) void proj_kv_kernel(
    const float* __restrict__ mdata, const float* __restrict__ key_w,
    const float* __restrict__ value_w)
{
    const int rowBase = blockIdx.y * BM;
    const int n0 = blockIdx.x * BN;
    const bool isV = (n0 >= 256);
    const float* W = isV ? value_w : key_w;
    const int nColBase = isV ? (n0 - 256) : n0;

    float acc[2][4][4];
    gemm_core_mma(mdata, W, rowBase, nColBase, acc);

    const int t = threadIdx.x, lane = t & 31, wid = t >> 5;
    const int g = lane >> 2, tg = lane & 3;
    const int mBase = (wid & 3) * 32, nBase = (wid >> 2) * 32;
#pragma unroll
    for (int mf = 0; mf < 2; mf++)
#pragma unroll
        for (int nf = 0; nf < 4; nf++)
#pragma unroll
            for (int r = 0; r < 4; r++) {
                int row = rowBase + mBase + mf * 16 + ((r & 2) ? 8 : 0) + g;
                int n   = nColBase + nBase + nf * 8 + tg * 2 + (r & 1);
                int b = row / NK, ki = row % NK;
                int h = n >> 5, c = n & 31;
                size_t idx = ((size_t)(b * NH + h) * NK + ki) * CDIM + c;
                if (!isV) g_k[idx] = acc[mf][nf][r];
                else      g_v[idx] = acc[mf][nf][r];
            }
}

// bias2 = bias + broadcast(nonbatched_bias)   (float4 vectorized)
__global__ __launch_bounds__(256) void bias_add_kernel(
    const float* __restrict__ bias, const float* __restrict__ nb)
{
    size_t s = (size_t)blockIdx.x * blockDim.x + threadIdx.x;  // float4 index
    const size_t n4 = (size_t)BDIM * NQ * NK / 4;
    if (s >= n4) return;
    const size_t per_b4 = (size_t)NQ * NK / 4;
    size_t rem = s % per_b4;
    float4 bv = ((const float4*)bias)[s];
    float4 nv = ((const float4*)nb)[rem];
    bv.x += nv.x; bv.y += nv.y; bv.z += nv.z; bv.w += nv.w;
    ((float4*)g_bias2)[s] = bv;
}

// fast exp(x) for x <= 0 (polynomial 2^f on the FMA pipe)
__device__ __forceinline__ float fexp(float x)
{
    float t = fmaxf(x * 1.4426950408889634f, -126.f);
    float n = floorf(t);
    float f = t - n;
    float p = 1.5403530e-4f;
    p = fmaf(p, f, 1.3333558e-3f);
    p = fmaf(p, f, 9.6181291e-3f);
    p = fmaf(p, f, 5.5504109e-2f);
    p = fmaf(p, f, 2.4022651e-1f);
    p = fmaf(p, f, 6.9314718e-1f);
    p = fmaf(p, f, 1.0f);
    float s = __int_as_float(((int)n + 127) << 23);
    return p * s;
}

// Attention: one block per (b,h); 384 threads, one q-row per thread.
// K/V staged in SMEM; bias staged per 32-wide j-tile (coalesced, transposed).
__global__ __launch_bounds__(384) void attn_kernel()
{
    const int bh = blockIdx.x;
    const int b = bh >> 3, h = bh & 7;
    extern __shared__ float sh[];
    float* ksh = sh;                         // [384][32]
    float* vsh = sh + NK * CDIM;             // [384][32]
    float* bsh = sh + 2 * NK * CDIM;         // [JT][BPAD]  (j-major, padded)

    const float4* kg = (const float4*)(g_k + (size_t)bh * NK * CDIM);
    const float4* vg = (const float4*)(g_v + (size_t)bh * NK * CDIM);
    const int tid = threadIdx.x;
    for (int s = tid; s < NK * CDIM / 4; s += 384) {
        ((float4*)ksh)[s] = kg[s];
        ((float4*)vsh)[s] = vg[s];
    }

    const int i = tid; // q row
    float q[32];
    const float4* qrow = (const float4*)(g_q + ((size_t)bh * NQ + i) * CDIM);
#pragma unroll
    for (int c8 = 0; c8 < 8; c8++) {
        float4 v4 = qrow[c8];
        q[c8 * 4 + 0] = v4.x; q[c8 * 4 + 1] = v4.y;
        q[c8 * 4 + 2] = v4.z; q[c8 * 4 + 3] = v4.w;
    }

    const float* bias2 = g_bias2 + (size_t)b * NQ * NK;

    float m = -1e30f, sum = 0.f;
    float acc[32];
#pragma unroll
    for (int c = 0; c < 32; c++) acc[c] = 0.f;

    for (int jt = 0; jt < NK; jt += JT) {
        __syncthreads();   // previous bias tile consumed (covers K/V staging on iter 0)
#pragma unroll
        for (int l = 0; l < 8; l++) {
            int s   = tid + l * 384;
            int r   = s >> 3;            // q row 0..383
            int seg = s & 7;             // 4-j segment
            float4 bv = *(const float4*)(bias2 + (size_t)r * NK + jt + seg * 4);
            bsh[(seg * 4 + 0) * BPAD + r] = bv.x;
            bsh[(seg * 4 + 1) * BPAD + r] = bv.y;
            bsh[(seg * 4 + 2) * BPAD + r] = bv.z;
            bsh[(seg * 4 + 3) * BPAD + r] = bv.w;
        }
        __syncthreads();

#pragma unroll 4
        for (int jj = 0; jj < JT; jj++) {
            const int j = jt + jj;
            const float4* kj = (const float4*)(ksh + j * CDIM);
            float s0 = 0.f, s1 = 0.f, s2 = 0.f, s3 = 0.f;
#pragma unroll
            for (int c8 = 0; c8 < 8; c8++) {
                float4 kv = kj[c8];
                s0 = fmaf(q[c8 * 4 + 0], kv.x, s0);
                s1 = fmaf(q[c8 * 4 + 1], kv.y, s1);
                s2 = fmaf(q[c8 * 4 + 2], kv.z, s2);
                s3 = fmaf(q[c8 * 4 + 3], kv.w, s3);
            }
            float sc = (s0 + s1) + (s2 + s3) + bsh[jj * BPAD + i];
            float p;
            if (sc > m) {
                float corr = fexp(m - sc);
                sum *= corr;
#pragma unroll
                for (int c = 0; c < 32; c++) acc[c] *= corr;
                m = sc;
                p = 1.f;
            } else {
                p = fexp(sc - m);
            }
            sum += p;
            const float4* vj = (const float4*)(vsh + j * CDIM);
#pragma unroll
            for (int c8 = 0; c8 < 8; c8++) {
                float4 vv = vj[c8];
                acc[c8 * 4 + 0] = fmaf(p, vv.x, acc[c8 * 4 + 0]);
                acc[c8 * 4 + 1] = fmaf(p, vv.y, acc[c8 * 4 + 1]);
                acc[c8 * 4 + 2] = fmaf(p, vv.z, acc[c8 * 4 + 2]);
                acc[c8 * 4 + 3] = fmaf(p, vv.w, acc[c8 * 4 + 3]);
            }
        }
    }

    float inv = 1.f / sum;
    const float4* grow = (const float4*)(g_gate + ((size_t)bh * NQ + i) * CDIM);
    float4* wrow = (float4*)(g_wg + (((size_t)b * NQ + i) * NH + h) * CDIM);
#pragma unroll
    for (int c8 = 0; c8 < 8; c8++) {
        float4 gv = grow[c8];
        float4 o;
        o.x = acc[c8 * 4 + 0] * inv * gv.x;
        o.y = acc[c8 * 4 + 1] * inv * gv.y;
        o.z = acc[c8 * 4 + 2] * inv * gv.z;
        o.w = acc[c8 * 4 + 3] * inv * gv.w;
        wrow[c8] = o;
    }
}

// Output projection: wg[49152,256] x output_w[256,256] + output_b. grid (4,384)
__global__ __launch_bounds__(256) void out_kernel(
    const float* __restrict__ output_w, const float* __restrict__ output_b,
    float* __restrict__ out)
{
    const int rowBase = blockIdx.y * BM;
    const int n0 = blockIdx.x * BN;
    float acc[2][4][4];
    gemm_core_mma(g_wg, output_w, rowBase, n0, acc);

    const int t = threadIdx.x, lane = t & 31, wid = t >> 5;
    const int g = lane >> 2, tg = lane & 3;
    const int mBase = (wid & 3) * 32, nBase = (wid >> 2) * 32;
#pragma unroll
    for (int mf = 0; mf < 2; mf++)
#pragma unroll
        for (int nf = 0; nf < 4; nf++)
#pragma unroll
            for (int r = 0; r < 4; r++) {
                int row = rowBase + mBase + mf * 16 + ((r & 2) ? 8 : 0) + g;
                int n   = n0 + nBase + nf * 8 + tg * 2 + (r & 1);
                out[(size_t)row * ODIM + n] = acc[mf][nf][r] + output_b[n];
            }
}

extern "C" void kernel_launch(void* const* d_in, const int* in_sizes, int n_in,
                              void* d_out, int out_size)
{
    const float* q_data   = (const float*)d_in[0];
    const float* m_data   = (const float*)d_in[1];
    const float* bias     = (const float*)d_in[2];
    const float* nbias    = (const float*)d_in[3];
    const float* query_w  = (const float*)d_in[4];
    const float* key_w    = (const float*)d_in[5];
    const float* value_w  = (const float*)d_in[6];
    const float* gating_w = (const float*)d_in[7];
    const float* gating_b = (const float*)d_in[8];
    const float* output_w = (const float*)d_in[9];
    const float* output_b = (const float*)d_in[10];
    float* out = (float*)d_out;

    const int smem_attn = (2 * NK * CDIM + JT * BPAD) * (int)sizeof(float); // ~147.5 KB
    cudaFuncSetAttribute(attn_kernel, cudaFuncAttributeMaxDynamicSharedMemorySize, smem_attn);

    dim3 gproj(8, MROWS / BM);
    proj_qg_kernel<<<gproj, 256>>>(q_data, query_w, gating_w, gating_b);
    proj_kv_kernel<<<gproj, 256>>>(m_data, key_w, value_w);
    {
        size_t n4 = (size_t)BDIM * NQ * NK / 4;
        int blocks = (int)((n4 + 255) / 256);
        bias_add_kernel<<<blocks, 256>>>(bias, nbias);
    }
    attn_kernel<<<BDIM * NH, 384, smem_attn>>>();
    dim3 gout(4, MROWS / BM);
    out_kernel<<<gout, 256>>>(output_w, output_b, out);
}

// round 4
// speedup vs baseline: 2.1957x; 1.1836x over previous
#include <cuda_runtime.h>
#include <math.h>

#define BDIM 128
#define NQ 384
#define NK 384
#define NH 8
#define CDIM 32
#define ADIM 256
#define ODIM 256
#define MROWS (BDIM*NQ)   // 49152

#define BM 128
#define BN 64
#define BK 16
#define ASTRIDE 20        // proj As[m][k] padded k-stride
#define WSTRIDE 72        // proj Ws[k][n] padded n-stride

// attention tiling
#define TQ 128
#define TJ 64
#define QSTR 36           // Qs [128][36]
#define KSTR 36           // Ks [64][36]
#define VSTR 68           // Vts [32][68]  (V transposed)
#define PSTR 68           // Ps/Bias [128][68] (aliased)

// Scratch (allocation-free rule: __device__ globals)
__device__ float g_q[(size_t)BDIM*NH*NQ*CDIM];
__device__ float g_k[(size_t)BDIM*NH*NK*CDIM];
__device__ float g_v[(size_t)BDIM*NH*NK*CDIM];
__device__ float g_gate[(size_t)BDIM*NH*NQ*CDIM];
__device__ float g_wg[(size_t)BDIM*NQ*NH*CDIM];

// ---------------------------------------------------------------------------
// tf32 helpers
// ---------------------------------------------------------------------------
__device__ __forceinline__ float to_tf32(float x)
{
    float r;
    asm("cvt.rna.tf32.f32 %0, %1;" : "=f"(r) : "f"(x));
    return r;
}

__device__ __forceinline__ void mma_tf32(float d[4], const unsigned a[4], const unsigned b[2])
{
    asm volatile(
        "mma.sync.aligned.m16n8k8.row.col.f32.tf32.tf32.f32 "
        "{%0,%1,%2,%3}, {%4,%5,%6,%7}, {%8,%9}, {%0,%1,%2,%3};"
        : "+f"(d[0]), "+f"(d[1]), "+f"(d[2]), "+f"(d[3])
        : "r"(a[0]), "r"(a[1]), "r"(a[2]), "r"(a[3]),
          "r"(b[0]), "r"(b[1]));
}

// ---------------------------------------------------------------------------
// tf32 MMA GEMM core: C[128x64] tile of A[MROWS,256] x W[256, nColBase+64]
// ---------------------------------------------------------------------------
__device__ __forceinline__ void gemm_core_mma(
    const float* __restrict__ A, const float* __restrict__ W,
    int rowBase, int nColBase, float acc[2][4][4])
{
    __shared__ float As[BM][ASTRIDE];
    __shared__ float Ws[BK][WSTRIDE];
    const int t    = threadIdx.x;
    const int lane = t & 31;
    const int wid  = t >> 5;
    const int g    = lane >> 2;
    const int tg   = lane & 3;
    const int mBase = (wid & 3) * 32;
    const int nBase = (wid >> 2) * 32;

#pragma unroll
    for (int mf = 0; mf < 2; mf++)
#pragma unroll
        for (int nf = 0; nf < 4; nf++)
#pragma unroll
            for (int r = 0; r < 4; r++) acc[mf][nf][r] = 0.f;

    for (int k0 = 0; k0 < ADIM; k0 += BK) {
#pragma unroll
        for (int l = 0; l < 2; l++) {
            int s  = t + l * 256;
            int m  = s >> 2;
            int kk = (s & 3) << 2;
            float4 av = *(const float4*)(A + (size_t)(rowBase + m) * ADIM + k0 + kk);
            As[m][kk + 0] = to_tf32(av.x);
            As[m][kk + 1] = to_tf32(av.y);
            As[m][kk + 2] = to_tf32(av.z);
            As[m][kk + 3] = to_tf32(av.w);
        }
        {
            int k  = t >> 4;
            int n4 = (t & 15) << 2;
            float4 wv = *(const float4*)(W + (size_t)(k0 + k) * 256 + nColBase + n4);
            Ws[k][n4 + 0] = to_tf32(wv.x);
            Ws[k][n4 + 1] = to_tf32(wv.y);
            Ws[k][n4 + 2] = to_tf32(wv.z);
            Ws[k][n4 + 3] = to_tf32(wv.w);
        }
        __syncthreads();

#pragma unroll
        for (int ks = 0; ks < BK; ks += 8) {
            unsigned a[2][4], b[4][2];
#pragma unroll
            for (int mf = 0; mf < 2; mf++) {
                int m0 = mBase + mf * 16 + g;
                a[mf][0] = __float_as_uint(As[m0    ][ks + tg    ]);
                a[mf][1] = __float_as_uint(As[m0 + 8][ks + tg    ]);
                a[mf][2] = __float_as_uint(As[m0    ][ks + tg + 4]);
                a[mf][3] = __float_as_uint(As[m0 + 8][ks + tg + 4]);
            }
#pragma unroll
            for (int nf = 0; nf < 4; nf++) {
                int n0 = nBase + nf * 8 + g;
                b[nf][0] = __float_as_uint(Ws[ks + tg    ][n0]);
                b[nf][1] = __float_as_uint(Ws[ks + tg + 4][n0]);
            }
#pragma unroll
            for (int mf = 0; mf < 2; mf++)
#pragma unroll
                for (int nf = 0; nf < 4; nf++)
                    mma_tf32(acc[mf][nf], a[mf], b[nf]);
        }
        __syncthreads();
    }
}

// q & gate projection: grid (8, 384). cols [0,256)=q (scaled), [256,512)=gate
__global__ __launch_bounds__(256) void proj_qg_kernel(
    const float* __restrict__ qdata, const float* __restrict__ query_w,
    const float* __restrict__ gating_w, const float* __restrict__ gating_b)
{
    const int rowBase = blockIdx.y * BM;
    const int n0 = blockIdx.x * BN;
    const bool isGate = (n0 >= 256);
    const float* W = isGate ? gating_w : query_w;
    const int nColBase = isGate ? (n0 - 256) : n0;

    float acc[2][4][4];
    gemm_core_mma(qdata, W, rowBase, nColBase, acc);

    const float scale = 0.17677669529663687f; // 1/sqrt(32)
    const int t = threadIdx.x, lane = t & 31, wid = t >> 5;
    const int g = lane >> 2, tg = lane & 3;
    const int mBase = (wid & 3) * 32, nBase = (wid >> 2) * 32;
#pragma unroll
    for (int mf = 0; mf < 2; mf++)
#pragma unroll
        for (int nf = 0; nf < 4; nf++)
#pragma unroll
            for (int r = 0; r < 4; r++) {
                int row = rowBase + mBase + mf * 16 + ((r & 2) ? 8 : 0) + g;
                int n   = nColBase + nBase + nf * 8 + tg * 2 + (r & 1);
                int b = row / NQ, qi = row % NQ;
                int h = n >> 5, c = n & 31;
                size_t idx = ((size_t)(b * NH + h) * NQ + qi) * CDIM + c;
                if (!isGate) {
                    g_q[idx] = acc[mf][nf][r] * scale;
                } else {
                    float x = acc[mf][nf][r] + gating_b[n];
                    g_gate[idx] = 1.f / (1.f + __expf(-x));
                }
            }
}

// k & v projection: grid (8, 384). cols [0,256)=k, [256,512)=v
__global__ __launch_bounds__(256) void proj_kv_kernel(
    const float* __restrict__ mdata, const float* __restrict__ key_w,
    const float* __restrict__ value_w)
{
    const int rowBase = blockIdx.y * BM;
    const int n0 = blockIdx.x * BN;
    const bool isV = (n0 >= 256);
    const float* W = isV ? value_w : key_w;
    const int nColBase = isV ? (n0 - 256) : n0;

    float acc[2][4][4];
    gemm_core_mma(mdata, W, rowBase, nColBase, acc);

    const int t = threadIdx.x, lane = t & 31, wid = t >> 5;
    const int g = lane >> 2, tg = lane & 3;
    const int mBase = (wid & 3) * 32, nBase = (wid >> 2) * 32;
#pragma unroll
    for (int mf = 0; mf < 2; mf++)
#pragma unroll
        for (int nf = 0; nf < 4; nf++)
#pragma unroll
            for (int r = 0; r < 4; r++) {
                int row = rowBase + mBase + mf * 16 + ((r & 2) ? 8 : 0) + g;
                int n   = nColBase + nBase + nf * 8 + tg * 2 + (r & 1);
                int b = row / NK, ki = row % NK;
                int h = n >> 5, c = n & 31;
                size_t idx = ((size_t)(b * NH + h) * NK + ki) * CDIM + c;
                if (!isV) g_k[idx] = acc[mf][nf][r];
                else      g_v[idx] = acc[mf][nf][r];
            }
}

// fast exp(x) for x <= 0 (polynomial 2^f on the FMA pipe)
__device__ __forceinline__ float fexp(float x)
{
    float t = fmaxf(x * 1.4426950408889634f, -126.f);
    float n = floorf(t);
    float f = t - n;
    float p = 1.5403530e-4f;
    p = fmaf(p, f, 1.3333558e-3f);
    p = fmaf(p, f, 9.6181291e-3f);
    p = fmaf(p, f, 5.5504109e-2f);
    p = fmaf(p, f, 2.4022651e-1f);
    p = fmaf(p, f, 6.9314718e-1f);
    p = fmaf(p, f, 1.0f);
    float s = __int_as_float(((int)n + 127) << 23);
    return p * s;
}

// ---------------------------------------------------------------------------
// Tensor-core flash attention. grid (NQ/TQ, BDIM*NH), 256 threads (8 warps).
// Warp w owns q-rows [16w, 16w+16) of the CTA's 128-row tile.
// S = QK^T (tf32 mma), +bias, online softmax on fragments, O += P V (tf32 mma).
// Bias tile and P tile share one SMEM region (warp-private rows).
// ---------------------------------------------------------------------------
__global__ void __launch_bounds__(256, 2) attn_mma_kernel(
    const float* __restrict__ bias, const float* __restrict__ nb)
{
    const int qt = blockIdx.x;          // q-tile 0..2
    const int bh = blockIdx.y;          // 0..1023
    const int b = bh >> 3, h = bh & 7;
    const int qBase = qt * TQ;

    extern __shared__ float sh[];
    float* Qs  = sh;                     // [128][QSTR]
    float* Ks  = Qs  + TQ * QSTR;        // [64][KSTR]
    float* Vts = Ks  + TJ * KSTR;        // [32][VSTR]
    float* Ps  = Vts + CDIM * VSTR;      // [128][PSTR]  bias/P alias

    const int tid  = threadIdx.x;
    const int lane = tid & 31, wid = tid >> 5;
    const int g = lane >> 2, tg = lane & 3;
    const int m0 = wid * 16;

    // ---- stage Q tile (tf32) ----
    const float* qg = g_q + ((size_t)bh * NQ + qBase) * CDIM;
#pragma unroll
    for (int l = 0; l < 4; l++) {
        int s = tid + l * 256;           // float4 slot
        int r = s >> 3, c4 = (s & 7) * 4;
        float4 v = *(const float4*)(qg + (size_t)r * CDIM + c4);
        Qs[r * QSTR + c4 + 0] = to_tf32(v.x);
        Qs[r * QSTR + c4 + 1] = to_tf32(v.y);
        Qs[r * QSTR + c4 + 2] = to_tf32(v.z);
        Qs[r * QSTR + c4 + 3] = to_tf32(v.w);
    }
    __syncthreads();

    // Q fragments, register resident for whole CTA lifetime
    unsigned qa[4][4];
#pragma unroll
    for (int kc = 0; kc < 4; kc++) {
        int ks = kc * 8;
        qa[kc][0] = __float_as_uint(Qs[(m0 + g    ) * QSTR + ks + tg    ]);
        qa[kc][1] = __float_as_uint(Qs[(m0 + g + 8) * QSTR + ks + tg    ]);
        qa[kc][2] = __float_as_uint(Qs[(m0 + g    ) * QSTR + ks + tg + 4]);
        qa[kc][3] = __float_as_uint(Qs[(m0 + g + 8) * QSTR + ks + tg + 4]);
    }

    float oacc[4][4];
#pragma unroll
    for (int nf = 0; nf < 4; nf++)
#pragma unroll
        for (int r = 0; r < 4; r++) oacc[nf][r] = 0.f;
    float mrow0 = -1e30f, mrow1 = -1e30f, lrow0 = 0.f, lrow1 = 0.f;

    const float* kgp = g_k + (size_t)bh * NK * CDIM;
    const float* vgp = g_v + (size_t)bh * NK * CDIM;
    const float* bgp = bias + ((size_t)b * NQ + qBase) * NK;
    const float* ngp = nb + (size_t)qBase * NK;

    for (int jt = 0; jt < NK; jt += TJ) {
        __syncthreads();   // previous Ps fully consumed by PV before overwrite
        // K tile [64][32] -> Ks (tf32)
#pragma unroll
        for (int l = 0; l < 2; l++) {
            int s = tid + l * 256;
            int r = s >> 3, c4 = (s & 7) * 4;
            float4 v = *(const float4*)(kgp + (size_t)(jt + r) * CDIM + c4);
            Ks[r * KSTR + c4 + 0] = to_tf32(v.x);
            Ks[r * KSTR + c4 + 1] = to_tf32(v.y);
            Ks[r * KSTR + c4 + 2] = to_tf32(v.z);
            Ks[r * KSTR + c4 + 3] = to_tf32(v.w);
        }
        // V tile [64][32] -> Vts transposed [32][64] (tf32)
#pragma unroll
        for (int l = 0; l < 2; l++) {
            int s = tid + l * 256;
            int r = s >> 3, c4 = (s & 7) * 4;
            float4 v = *(const float4*)(vgp + (size_t)(jt + r) * CDIM + c4);
            Vts[(c4 + 0) * VSTR + r] = to_tf32(v.x);
            Vts[(c4 + 1) * VSTR + r] = to_tf32(v.y);
            Vts[(c4 + 2) * VSTR + r] = to_tf32(v.z);
            Vts[(c4 + 3) * VSTR + r] = to_tf32(v.w);
        }
        // bias tile [128 q][64 j] (+ nonbatched) -> Ps
#pragma unroll
        for (int l = 0; l < 8; l++) {
            int s = tid + l * 256;
            int r = s >> 4, c4 = (s & 15) * 4;
            float4 bv = *(const float4*)(bgp + (size_t)r * NK + jt + c4);
            float4 nv = *(const float4*)(ngp + (size_t)r * NK + jt + c4);
            Ps[r * PSTR + c4 + 0] = bv.x + nv.x;
            Ps[r * PSTR + c4 + 1] = bv.y + nv.y;
            Ps[r * PSTR + c4 + 2] = bv.z + nv.z;
            Ps[r * PSTR + c4 + 3] = bv.w + nv.w;
        }
        __syncthreads();

        // S = Q K^T : sf[8 nf][4]
        float sf[8][4];
#pragma unroll
        for (int nf = 0; nf < 8; nf++)
#pragma unroll
            for (int r = 0; r < 4; r++) sf[nf][r] = 0.f;
#pragma unroll
        for (int kc = 0; kc < 4; kc++) {
            int ks = kc * 8;
            unsigned bf[8][2];
#pragma unroll
            for (int nf = 0; nf < 8; nf++) {
                bf[nf][0] = __float_as_uint(Ks[(nf * 8 + g) * KSTR + ks + tg    ]);
                bf[nf][1] = __float_as_uint(Ks[(nf * 8 + g) * KSTR + ks + tg + 4]);
            }
#pragma unroll
            for (int nf = 0; nf < 8; nf++)
                mma_tf32(sf[nf], qa[kc], bf[nf]);
        }
        // + bias (warp-private rows of Ps)
#pragma unroll
        for (int nf = 0; nf < 8; nf++) {
            float2 b01 = *(const float2*)&Ps[(m0 + g    ) * PSTR + nf * 8 + 2 * tg];
            float2 b23 = *(const float2*)&Ps[(m0 + g + 8) * PSTR + nf * 8 + 2 * tg];
            sf[nf][0] += b01.x; sf[nf][1] += b01.y;
            sf[nf][2] += b23.x; sf[nf][3] += b23.y;
        }
        // row maxima (rows g, g+8)
        float mx0 = -1e30f, mx1 = -1e30f;
#pragma unroll
        for (int nf = 0; nf < 8; nf++) {
            mx0 = fmaxf(mx0, fmaxf(sf[nf][0], sf[nf][1]));
            mx1 = fmaxf(mx1, fmaxf(sf[nf][2], sf[nf][3]));
        }
        mx0 = fmaxf(mx0, __shfl_xor_sync(0xffffffffu, mx0, 1));
        mx0 = fmaxf(mx0, __shfl_xor_sync(0xffffffffu, mx0, 2));
        mx1 = fmaxf(mx1, __shfl_xor_sync(0xffffffffu, mx1, 1));
        mx1 = fmaxf(mx1, __shfl_xor_sync(0xffffffffu, mx1, 2));
        float mn0 = fmaxf(mrow0, mx0), mn1 = fmaxf(mrow1, mx1);
        float cor0 = fexp(mrow0 - mn0), cor1 = fexp(mrow1 - mn1);
        mrow0 = mn0; mrow1 = mn1;
        lrow0 *= cor0; lrow1 *= cor1;
#pragma unroll
        for (int nf = 0; nf < 4; nf++) {
            oacc[nf][0] *= cor0; oacc[nf][1] *= cor0;
            oacc[nf][2] *= cor1; oacc[nf][3] *= cor1;
        }
        // p = exp(s-m), accumulate row sums, store P (tf32) over bias region
        float s0 = 0.f, s1 = 0.f;
#pragma unroll
        for (int nf = 0; nf < 8; nf++) {
            float p0 = fexp(sf[nf][0] - mn0);
            float p1 = fexp(sf[nf][1] - mn0);
            float p2 = fexp(sf[nf][2] - mn1);
            float p3 = fexp(sf[nf][3] - mn1);
            s0 += p0 + p1; s1 += p2 + p3;
            float2 w01; w01.x = to_tf32(p0); w01.y = to_tf32(p1);
            float2 w23; w23.x = to_tf32(p2); w23.y = to_tf32(p3);
            *(float2*)&Ps[(m0 + g    ) * PSTR + nf * 8 + 2 * tg] = w01;
            *(float2*)&Ps[(m0 + g + 8) * PSTR + nf * 8 + 2 * tg] = w23;
        }
        s0 += __shfl_xor_sync(0xffffffffu, s0, 1);
        s0 += __shfl_xor_sync(0xffffffffu, s0, 2);
        s1 += __shfl_xor_sync(0xffffffffu, s1, 1);
        s1 += __shfl_xor_sync(0xffffffffu, s1, 2);
        lrow0 += s0; lrow1 += s1;

        __syncwarp();   // P stores visible to all lanes of this warp
        // O += P V
#pragma unroll
        for (int kc = 0; kc < 8; kc++) {
            int ks = kc * 8;
            unsigned pa[4];
            pa[0] = __float_as_uint(Ps[(m0 + g    ) * PSTR + ks + tg    ]);
            pa[1] = __float_as_uint(Ps[(m0 + g + 8) * PSTR + ks + tg    ]);
            pa[2] = __float_as_uint(Ps[(m0 + g    ) * PSTR + ks + tg + 4]);
            pa[3] = __float_as_uint(Ps[(m0 + g + 8) * PSTR + ks + tg + 4]);
            unsigned vb[4][2];
#pragma unroll
            for (int nf = 0; nf < 4; nf++) {
                vb[nf][0] = __float_as_uint(Vts[(nf * 8 + g) * VSTR + ks + tg    ]);
                vb[nf][1] = __float_as_uint(Vts[(nf * 8 + g) * VSTR + ks + tg + 4]);
            }
#pragma unroll
            for (int nf = 0; nf < 4; nf++)
                mma_tf32(oacc[nf], pa, vb[nf]);
        }
    }

    // epilogue: normalize, gate, write g_wg
    float inv0 = 1.f / lrow0, inv1 = 1.f / lrow1;
    int r0 = qBase + m0 + g, r1 = r0 + 8;
    const float* gate0 = g_gate + ((size_t)bh * NQ + r0) * CDIM;
    const float* gate1 = g_gate + ((size_t)bh * NQ + r1) * CDIM;
    float* w0 = g_wg + (((size_t)b * NQ + r0) * NH + h) * CDIM;
    float* w1 = g_wg + (((size_t)b * NQ + r1) * NH + h) * CDIM;
#pragma unroll
    for (int nf = 0; nf < 4; nf++) {
        int c = nf * 8 + 2 * tg;
        float2 ga = *(const float2*)(gate0 + c);
        float2 gb = *(const float2*)(gate1 + c);
        float2 oa, ob;
        oa.x = oacc[nf][0] * inv0 * ga.x;
        oa.y = oacc[nf][1] * inv0 * ga.y;
        ob.x = oacc[nf][2] * inv1 * gb.x;
        ob.y = oacc[nf][3] * inv1 * gb.y;
        *(float2*)(w0 + c) = oa;
        *(float2*)(w1 + c) = ob;
    }
}

// Output projection: wg[49152,256] x output_w[256,256] + output_b. grid (4,384)
__global__ __launch_bounds__(256) void out_kernel(
    const float* __restrict__ output_w, const float* __restrict__ output_b,
    float* __restrict__ out)
{
    const int rowBase = blockIdx.y * BM;
    const int n0 = blockIdx.x * BN;
    float acc[2][4][4];
    gemm_core_mma(g_wg, output_w, rowBase, n0, acc);

    const int t = threadIdx.x, lane = t & 31, wid = t >> 5;
    const int g = lane >> 2, tg = lane & 3;
    const int mBase = (wid & 3) * 32, nBase = (wid >> 2) * 32;
#pragma unroll
    for (int mf = 0; mf < 2; mf++)
#pragma unroll
        for (int nf = 0; nf < 4; nf++)
#pragma unroll
            for (int r = 0; r < 4; r++) {
                int row = rowBase + mBase + mf * 16 + ((r & 2) ? 8 : 0) + g;
                int n   = n0 + nBase + nf * 8 + tg * 2 + (r & 1);
                out[(size_t)row * ODIM + n] = acc[mf][nf][r] + output_b[n];
            }
}

extern "C" void kernel_launch(void* const* d_in, const int* in_sizes, int n_in,
                              void* d_out, int out_size)
{
    const float* q_data   = (const float*)d_in[0];
    const float* m_data   = (const float*)d_in[1];
    const float* bias     = (const float*)d_in[2];
    const float* nbias    = (const float*)d_in[3];
    const float* query_w  = (const float*)d_in[4];
    const float* key_w    = (const float*)d_in[5];
    const float* value_w  = (const float*)d_in[6];
    const float* gating_w = (const float*)d_in[7];
    const float* gating_b = (const float*)d_in[8];
    const float* output_w = (const float*)d_in[9];
    const float* output_b = (const float*)d_in[10];
    float* out = (float*)d_out;

    const int smem_attn = (TQ * QSTR + TJ * KSTR + CDIM * VSTR + TQ * PSTR)
                          * (int)sizeof(float);   // ~69.5 KB
    cudaFuncSetAttribute(attn_mma_kernel, cudaFuncAttributeMaxDynamicSharedMemorySize, smem_attn);

    dim3 gproj(8, MROWS / BM);
    proj_qg_kernel<<<gproj, 256>>>(q_data, query_w, gating_w, gating_b);
    proj_kv_kernel<<<gproj, 256>>>(m_data, key_w, value_w);
    dim3 gattn(NQ / TQ, BDIM * NH);
    attn_mma_kernel<<<gattn, 256, smem_attn>>>(bias, nbias);
    dim3 gout(4, MROWS / BM);
    out_kernel<<<gout, 256>>>(output_w, output_b, out);
}

// round 6
// speedup vs baseline: 4.2955x; 1.9563x over previous
#include <cuda_runtime.h>
#include <cuda_fp16.h>
#include <math.h>

#define BDIM 128
#define NQ 384
#define NK 384
#define NH 8
#define CDIM 32
#define ADIM 256
#define ODIM 256
#define MROWS (BDIM*NQ)   // 49152

#define BM 128
#define BN 64
#define BK 16
#define AS2 12            // As2[m][k2] half2 stride (8 data + 4 pad)
#define WS2 12            // Ws2[n][k2] half2 stride

// attention tiling
#define TQ 128
#define TJ 64
#define QS2 20            // Qs2[q][c2] (16 data + 4 pad)
#define KS2 20            // Ks2[j][c2]
#define VS2 36            // Vts2[c][j2] (32 data + 4 pad)
#define PS2 36            // P2[q][j2]
#define BSTR 68           // bias tile float stride

// Scratch (allocation-free rule: __device__ globals)
__device__ float g_q[(size_t)BDIM*NH*NQ*CDIM];
__device__ float g_k[(size_t)BDIM*NH*NK*CDIM];
__device__ float g_v[(size_t)BDIM*NH*NK*CDIM];
__device__ float g_gate[(size_t)BDIM*NH*NQ*CDIM];
__device__ float g_wg[(size_t)BDIM*NQ*NH*CDIM];
__device__ unsigned g_wt[5][256][128];   // packed W^T half2: [mat][n][k2]

__device__ __forceinline__ unsigned f2h2(float x, float y)
{
    __half2 h = __floats2half2_rn(x, y);
    return *(unsigned*)&h;
}

__device__ __forceinline__ void mma_f16(float d[4], const unsigned a[4], const unsigned b[2])
{
    asm volatile(
        "mma.sync.aligned.m16n8k16.row.col.f32.f16.f16.f32 "
        "{%0,%1,%2,%3}, {%4,%5,%6,%7}, {%8,%9}, {%0,%1,%2,%3};"
        : "+f"(d[0]), "+f"(d[1]), "+f"(d[2]), "+f"(d[3])
        : "r"(a[0]), "r"(a[1]), "r"(a[2]), "r"(a[3]),
          "r"(b[0]), "r"(b[1]));
}

// ---------------------------------------------------------------------------
// Pack weights: g_wt[mat][n][k2] = half2(W[2k2][n], W[2k2+1][n])
// grid (128, 5), block 256
// ---------------------------------------------------------------------------
__global__ __launch_bounds__(256) void pack_w_kernel(
    const float* __restrict__ qw, const float* __restrict__ gw,
    const float* __restrict__ kw, const float* __restrict__ vw,
    const float* __restrict__ ow)
{
    const int n  = threadIdx.x;
    const int k2 = blockIdx.x;
    const int mat = blockIdx.y;
    const float* W = (mat == 0) ? qw : (mat == 1) ? gw : (mat == 2) ? kw
                   : (mat == 3) ? vw : ow;
    float x = W[(size_t)(2 * k2) * 256 + n];
    float y = W[(size_t)(2 * k2 + 1) * 256 + n];
    g_wt[mat][n][k2] = f2h2(x, y);
}

// ---------------------------------------------------------------------------
// fp16 MMA GEMM core: C[128x64] tile of A[MROWS,256] x W[256, nColBase+64]
// A fp32 row-major; W via packed g_wt (half2 along k). 8 warps, warp 32x32.
// ---------------------------------------------------------------------------
__device__ __forceinline__ void gemm_core_f16(
    const float* __restrict__ A, const unsigned* __restrict__ Wt,
    int rowBase, int nColBase, float acc[2][4][4])
{
    __shared__ unsigned As2[BM][AS2];
    __shared__ unsigned Ws2[BN][WS2];
    const int t    = threadIdx.x;
    const int lane = t & 31;
    const int wid  = t >> 5;
    const int g    = lane >> 2;
    const int tg   = lane & 3;
    const int mBase = (wid & 3) * 32;
    const int nBase = (wid >> 2) * 32;

#pragma unroll
    for (int mf = 0; mf < 2; mf++)
#pragma unroll
        for (int nf = 0; nf < 4; nf++)
#pragma unroll
            for (int r = 0; r < 4; r++) acc[mf][nf][r] = 0.f;

    for (int k0 = 0; k0 < ADIM; k0 += BK) {
        // A tile: 128 rows x 16 k -> half2
#pragma unroll
        for (int l = 0; l < 2; l++) {
            int s  = t + l * 256;
            int m  = s >> 2;
            int kk = (s & 3) << 2;
            float4 av = *(const float4*)(A + (size_t)(rowBase + m) * ADIM + k0 + kk);
            As2[m][(kk >> 1)    ] = f2h2(av.x, av.y);
            As2[m][(kk >> 1) + 1] = f2h2(av.z, av.w);
        }
        // W tile: 64 n x 8 k2 from packed g_wt
#pragma unroll
        for (int l = 0; l < 2; l++) {
            int s   = t + l * 256;
            int n   = s >> 3;
            int k2l = s & 7;
            Ws2[n][k2l] = Wt[(size_t)(nColBase + n) * 128 + (k0 >> 1) + k2l];
        }
        __syncthreads();

        unsigned a[2][4], b[4][2];
#pragma unroll
        for (int mf = 0; mf < 2; mf++) {
            int m0 = mBase + mf * 16 + g;
            a[mf][0] = As2[m0    ][tg    ];
            a[mf][1] = As2[m0 + 8][tg    ];
            a[mf][2] = As2[m0    ][tg + 4];
            a[mf][3] = As2[m0 + 8][tg + 4];
        }
#pragma unroll
        for (int nf = 0; nf < 4; nf++) {
            int n0 = nBase + nf * 8 + g;
            b[nf][0] = Ws2[n0][tg    ];
            b[nf][1] = Ws2[n0][tg + 4];
        }
#pragma unroll
        for (int mf = 0; mf < 2; mf++)
#pragma unroll
            for (int nf = 0; nf < 4; nf++)
                mma_f16(acc[mf][nf], a[mf], b[nf]);
        __syncthreads();
    }
}

// q & gate projection: grid (8, 384). cols [0,256)=q (scaled), [256,512)=gate
__global__ __launch_bounds__(256) void proj_qg_kernel(
    const float* __restrict__ qdata, const float* __restrict__ gating_b)
{
    const int rowBase = blockIdx.y * BM;
    const int n0 = blockIdx.x * BN;
    const bool isGate = (n0 >= 256);
    const unsigned* Wt = isGate ? &g_wt[1][0][0] : &g_wt[0][0][0];
    const int nColBase = isGate ? (n0 - 256) : n0;

    float acc[2][4][4];
    gemm_core_f16(qdata, Wt, rowBase, nColBase, acc);

    const float scale = 0.17677669529663687f; // 1/sqrt(32)
    const int t = threadIdx.x, lane = t & 31, wid = t >> 5;
    const int g = lane >> 2, tg = lane & 3;
    const int mBase = (wid & 3) * 32, nBase = (wid >> 2) * 32;
#pragma unroll
    for (int mf = 0; mf < 2; mf++)
#pragma unroll
        for (int nf = 0; nf < 4; nf++)
#pragma unroll
            for (int r = 0; r < 4; r++) {
                int row = rowBase + mBase + mf * 16 + ((r & 2) ? 8 : 0) + g;
                int n   = nColBase + nBase + nf * 8 + tg * 2 + (r & 1);
                int b = row / NQ, qi = row % NQ;
                int h = n >> 5, c = n & 31;
                size_t idx = ((size_t)(b * NH + h) * NQ + qi) * CDIM + c;
                if (!isGate) {
                    g_q[idx] = acc[mf][nf][r] * scale;
                } else {
                    float x = acc[mf][nf][r] + gating_b[n];
                    g_gate[idx] = 1.f / (1.f + __expf(-x));
                }
            }
}

// k & v projection: grid (8, 384). cols [0,256)=k, [256,512)=v
__global__ __launch_bounds__(256) void proj_kv_kernel(
    const float* __restrict__ mdata)
{
    const int rowBase = blockIdx.y * BM;
    const int n0 = blockIdx.x * BN;
    const bool isV = (n0 >= 256);
    const unsigned* Wt = isV ? &g_wt[3][0][0] : &g_wt[2][0][0];
    const int nColBase = isV ? (n0 - 256) : n0;

    float acc[2][4][4];
    gemm_core_f16(mdata, Wt, rowBase, nColBase, acc);

    const int t = threadIdx.x, lane = t & 31, wid = t >> 5;
    const int g = lane >> 2, tg = lane & 3;
    const int mBase = (wid & 3) * 32, nBase = (wid >> 2) * 32;
#pragma unroll
    for (int mf = 0; mf < 2; mf++)
#pragma unroll
        for (int nf = 0; nf < 4; nf++)
#pragma unroll
            for (int r = 0; r < 4; r++) {
                int row = rowBase + mBase + mf * 16 + ((r & 2) ? 8 : 0) + g;
                int n   = nColBase + nBase + nf * 8 + tg * 2 + (r & 1);
                int b = row / NK, ki = row % NK;
                int h = n >> 5, c = n & 31;
                size_t idx = ((size_t)(b * NH + h) * NK + ki) * CDIM + c;
                if (!isV) g_k[idx] = acc[mf][nf][r];
                else      g_v[idx] = acc[mf][nf][r];
            }
}

// ---------------------------------------------------------------------------
// fp16 tensor-core flash attention. grid (NQ/TQ, BDIM*NH), 256 threads.
// Warp w owns q-rows [16w,16w+16). S=QK^T (f16 mma) + bias(f32), online
// softmax, O += P V (f16 mma). P stored as half2 (conflict-free).
// ---------------------------------------------------------------------------
__global__ void __launch_bounds__(256, 2) attn_mma_kernel(
    const float* __restrict__ bias, const float* __restrict__ nb)
{
    const int qt = blockIdx.x;
    const int bh = blockIdx.y;
    const int b = bh >> 3, h = bh & 7;
    const int qBase = qt * TQ;

    extern __shared__ float sh[];
    unsigned* Qs2  = (unsigned*)sh;          // [128][QS2]
    unsigned* Ks2  = Qs2 + TQ * QS2;         // [64][KS2]
    unsigned* Vts2 = Ks2 + TJ * KS2;         // [32][VS2]
    unsigned* P2   = Vts2 + CDIM * VS2;      // [128][PS2]
    float*    bsh  = (float*)(P2 + TQ * PS2);// [128][BSTR]

    const int tid  = threadIdx.x;
    const int lane = tid & 31, wid = tid >> 5;
    const int g = lane >> 2, tg = lane & 3;
    const int m0 = wid * 16;

    // ---- stage Q tile as half2 ----
    const float* qg = g_q + ((size_t)bh * NQ + qBase) * CDIM;
#pragma unroll
    for (int l = 0; l < 4; l++) {
        int s = tid + l * 256;           // float4 slot (128 rows x 8)
        int r = s >> 3, c4 = (s & 7) * 4;
        float4 v = *(const float4*)(qg + (size_t)r * CDIM + c4);
        Qs2[r * QS2 + (c4 >> 1)    ] = f2h2(v.x, v.y);
        Qs2[r * QS2 + (c4 >> 1) + 1] = f2h2(v.z, v.w);
    }
    __syncthreads();

    // Q fragments (2 k16 steps over CDIM=32), register resident
    unsigned qa[2][4];
#pragma unroll
    for (int kc = 0; kc < 2; kc++) {
        int ks2 = kc * 8;
        qa[kc][0] = Qs2[(m0 + g    ) * QS2 + ks2 + tg    ];
        qa[kc][1] = Qs2[(m0 + g + 8) * QS2 + ks2 + tg    ];
        qa[kc][2] = Qs2[(m0 + g    ) * QS2 + ks2 + tg + 4];
        qa[kc][3] = Qs2[(m0 + g + 8) * QS2 + ks2 + tg + 4];
    }

    float oacc[4][4];
#pragma unroll
    for (int nf = 0; nf < 4; nf++)
#pragma unroll
        for (int r = 0; r < 4; r++) oacc[nf][r] = 0.f;
    float mrow0 = -1e30f, mrow1 = -1e30f, lrow0 = 0.f, lrow1 = 0.f;

    const float* kgp = g_k + (size_t)bh * NK * CDIM;
    const float* vgp = g_v + (size_t)bh * NK * CDIM;
    const float* bgp = bias + ((size_t)b * NQ + qBase) * NK;
    const float* ngp = nb + (size_t)qBase * NK;

    for (int jt = 0; jt < NK; jt += TJ) {
        __syncthreads();   // prior tile fully consumed
        // K tile [64][32] -> Ks2 (half2 along c)
#pragma unroll
        for (int l = 0; l < 2; l++) {
            int s = tid + l * 256;
            int r = s >> 3, c4 = (s & 7) * 4;
            float4 v = *(const float4*)(kgp + (size_t)(jt + r) * CDIM + c4);
            Ks2[r * KS2 + (c4 >> 1)    ] = f2h2(v.x, v.y);
            Ks2[r * KS2 + (c4 >> 1) + 1] = f2h2(v.z, v.w);
        }
        // V tile [64][32] -> Vts2 [c][j2] transposed, half2 along j
        {
            int r2 = tid >> 3;           // j-pair 0..31
            int c4 = (tid & 7) * 4;
            float4 v0 = *(const float4*)(vgp + (size_t)(jt + 2 * r2    ) * CDIM + c4);
            float4 v1 = *(const float4*)(vgp + (size_t)(jt + 2 * r2 + 1) * CDIM + c4);
            Vts2[(c4 + 0) * VS2 + r2] = f2h2(v0.x, v1.x);
            Vts2[(c4 + 1) * VS2 + r2] = f2h2(v0.y, v1.y);
            Vts2[(c4 + 2) * VS2 + r2] = f2h2(v0.z, v1.z);
            Vts2[(c4 + 3) * VS2 + r2] = f2h2(v0.w, v1.w);
        }
        // bias tile [128 q][64 j] (+ nonbatched) fp32 -> bsh
#pragma unroll
        for (int l = 0; l < 8; l++) {
            int s = tid + l * 256;
            int r = s >> 4, c4 = (s & 15) * 4;
            float4 bv = *(const float4*)(bgp + (size_t)r * NK + jt + c4);
            float4 nv = *(const float4*)(ngp + (size_t)r * NK + jt + c4);
            bsh[r * BSTR + c4 + 0] = bv.x + nv.x;
            bsh[r * BSTR + c4 + 1] = bv.y + nv.y;
            bsh[r * BSTR + c4 + 2] = bv.z + nv.z;
            bsh[r * BSTR + c4 + 3] = bv.w + nv.w;
        }
        __syncthreads();

        // S = Q K^T : sf[8 nf][4]
        float sf[8][4];
#pragma unroll
        for (int nf = 0; nf < 8; nf++)
#pragma unroll
            for (int r = 0; r < 4; r++) sf[nf][r] = 0.f;
#pragma unroll
        for (int kc = 0; kc < 2; kc++) {
            int ks2 = kc * 8;
            unsigned bf[8][2];
#pragma unroll
            for (int nf = 0; nf < 8; nf++) {
                bf[nf][0] = Ks2[(nf * 8 + g) * KS2 + ks2 + tg    ];
                bf[nf][1] = Ks2[(nf * 8 + g) * KS2 + ks2 + tg + 4];
            }
#pragma unroll
            for (int nf = 0; nf < 8; nf++)
                mma_f16(sf[nf], qa[kc], bf[nf]);
        }
        // + bias
#pragma unroll
        for (int nf = 0; nf < 8; nf++) {
            float2 b01 = *(const float2*)&bsh[(m0 + g    ) * BSTR + nf * 8 + 2 * tg];
            float2 b23 = *(const float2*)&bsh[(m0 + g + 8) * BSTR + nf * 8 + 2 * tg];
            sf[nf][0] += b01.x; sf[nf][1] += b01.y;
            sf[nf][2] += b23.x; sf[nf][3] += b23.y;
        }
        // row maxima
        float mx0 = -1e30f, mx1 = -1e30f;
#pragma unroll
        for (int nf = 0; nf < 8; nf++) {
            mx0 = fmaxf(mx0, fmaxf(sf[nf][0], sf[nf][1]));
            mx1 = fmaxf(mx1, fmaxf(sf[nf][2], sf[nf][3]));
        }
        mx0 = fmaxf(mx0, __shfl_xor_sync(0xffffffffu, mx0, 1));
        mx0 = fmaxf(mx0, __shfl_xor_sync(0xffffffffu, mx0, 2));
        mx1 = fmaxf(mx1, __shfl_xor_sync(0xffffffffu, mx1, 1));
        mx1 = fmaxf(mx1, __shfl_xor_sync(0xffffffffu, mx1, 2));
        float mn0 = fmaxf(mrow0, mx0), mn1 = fmaxf(mrow1, mx1);
        float cor0 = __expf(mrow0 - mn0), cor1 = __expf(mrow1 - mn1);
        mrow0 = mn0; mrow1 = mn1;
        lrow0 *= cor0; lrow1 *= cor1;
#pragma unroll
        for (int nf = 0; nf < 4; nf++) {
            oacc[nf][0] *= cor0; oacc[nf][1] *= cor0;
            oacc[nf][2] *= cor1; oacc[nf][3] *= cor1;
        }
        // p = exp(s-m) -> half2 P, accumulate row sums
        float s0 = 0.f, s1 = 0.f;
#pragma unroll
        for (int nf = 0; nf < 8; nf++) {
            float p0 = __expf(sf[nf][0] - mn0);
            float p1 = __expf(sf[nf][1] - mn0);
            float p2 = __expf(sf[nf][2] - mn1);
            float p3 = __expf(sf[nf][3] - mn1);
            s0 += p0 + p1; s1 += p2 + p3;
            P2[(m0 + g    ) * PS2 + nf * 4 + tg] = f2h2(p0, p1);
            P2[(m0 + g + 8) * PS2 + nf * 4 + tg] = f2h2(p2, p3);
        }
        s0 += __shfl_xor_sync(0xffffffffu, s0, 1);
        s0 += __shfl_xor_sync(0xffffffffu, s0, 2);
        s1 += __shfl_xor_sync(0xffffffffu, s1, 1);
        s1 += __shfl_xor_sync(0xffffffffu, s1, 2);
        lrow0 += s0; lrow1 += s1;

        __syncwarp();   // P2 warp-private rows visible
        // O += P V  (4 k16 steps over 64 j)
#pragma unroll
        for (int kc = 0; kc < 4; kc++) {
            int ks2 = kc * 8;
            unsigned pa[4];
            pa[0] = P2[(m0 + g    ) * PS2 + ks2 + tg    ];
            pa[1] = P2[(m0 + g + 8) * PS2 + ks2 + tg    ];
            pa[2] = P2[(m0 + g    ) * PS2 + ks2 + tg + 4];
            pa[3] = P2[(m0 + g + 8) * PS2 + ks2 + tg + 4];
            unsigned vb[4][2];
#pragma unroll
            for (int nf = 0; nf < 4; nf++) {
                vb[nf][0] = Vts2[(nf * 8 + g) * VS2 + ks2 + tg    ];
                vb[nf][1] = Vts2[(nf * 8 + g) * VS2 + ks2 + tg + 4];
            }
#pragma unroll
            for (int nf = 0; nf < 4; nf++)
                mma_f16(oacc[nf], pa, vb[nf]);
        }
    }

    // epilogue: normalize, gate, write g_wg
    float inv0 = 1.f / lrow0, inv1 = 1.f / lrow1;
    int r0 = qBase + m0 + g, r1 = r0 + 8;
    const float* gate0 = g_gate + ((size_t)bh * NQ + r0) * CDIM;
    const float* gate1 = g_gate + ((size_t)bh * NQ + r1) * CDIM;
    float* w0 = g_wg + (((size_t)b * NQ + r0) * NH + h) * CDIM;
    float* w1 = g_wg + (((size_t)b * NQ + r1) * NH + h) * CDIM;
#pragma unroll
    for (int nf = 0; nf < 4; nf++) {
        int c = nf * 8 + 2 * tg;
        float2 ga = *(const float2*)(gate0 + c);
        float2 gb = *(const float2*)(gate1 + c);
        float2 oa, ob;
        oa.x = oacc[nf][0] * inv0 * ga.x;
        oa.y = oacc[nf][1] * inv0 * ga.y;
        ob.x = oacc[nf][2] * inv1 * gb.x;
        ob.y = oacc[nf][3] * inv1 * gb.y;
        *(float2*)(w0 + c) = oa;
        *(float2*)(w1 + c) = ob;
    }
}

// Output projection: wg[49152,256] x output_w[256,256] + output_b. grid (4,384)
__global__ __launch_bounds__(256) void out_kernel(
    const float* __restrict__ output_b, float* __restrict__ out)
{
    const int rowBase = blockIdx.y * BM;
    const int n0 = blockIdx.x * BN;
    float acc[2][4][4];
    gemm_core_f16(g_wg, &g_wt[4][0][0], rowBase, n0, acc);

    const int t = threadIdx.x, lane = t & 31, wid = t >> 5;
    const int g = lane >> 2, tg = lane & 3;
    const int mBase = (wid & 3) * 32, nBase = (wid >> 2) * 32;
#pragma unroll
    for (int mf = 0; mf < 2; mf++)
#pragma unroll
        for (int nf = 0; nf < 4; nf++)
#pragma unroll
            for (int r = 0; r < 4; r++) {
                int row = rowBase + mBase + mf * 16 + ((r & 2) ? 8 : 0) + g;
                int n   = n0 + nBase + nf * 8 + tg * 2 + (r & 1);
                out[(size_t)row * ODIM + n] = acc[mf][nf][r] + output_b[n];
            }
}

extern "C" void kernel_launch(void* const* d_in, const int* in_sizes, int n_in,
                              void* d_out, int out_size)
{
    const float* q_data   = (const float*)d_in[0];
    const float* m_data   = (const float*)d_in[1];
    const float* bias     = (const float*)d_in[2];
    const float* nbias    = (const float*)d_in[3];
    const float* query_w  = (const float*)d_in[4];
    const float* key_w    = (const float*)d_in[5];
    const float* value_w  = (const float*)d_in[6];
    const float* gating_w = (const float*)d_in[7];
    const float* gating_b = (const float*)d_in[8];
    const float* output_w = (const float*)d_in[9];
    const float* output_b = (const float*)d_in[10];
    float* out = (float*)d_out;

    const int smem_attn = (TQ * QS2 + TJ * KS2 + CDIM * VS2 + TQ * PS2) * 4
                          + TQ * BSTR * 4;   // ~71.5 KB
    cudaFuncSetAttribute(attn_mma_kernel, cudaFuncAttributeMaxDynamicSharedMemorySize, smem_attn);

    dim3 gpack(128, 5);
    pack_w_kernel<<<gpack, 256>>>(query_w, gating_w, key_w, value_w, output_w);

    dim3 gproj(8, MROWS / BM);
    proj_qg_kernel<<<gproj, 256>>>(q_data, gating_b);
    proj_kv_kernel<<<gproj, 256>>>(m_data);
    dim3 gattn(NQ / TQ, BDIM * NH);
    attn_mma_kernel<<<gattn, 256, smem_attn>>>(bias, nbias);
    dim3 gout(4, MROWS / BM);
    out_kernel<<<gout, 256>>>(output_b, out);
}

// round 7
// speedup vs baseline: 5.3805x; 1.2526x over previous
#include <cuda_runtime.h>
#include <cuda_fp16.h>
#include <math.h>

#define BDIM 128
#define NQ 384
#define NK 384
#define NH 8
#define CDIM 32
#define ADIM 256
#define ODIM 256
#define MROWS (BDIM*NQ)   // 49152

#define BM 128
#define BN 64
#define BK 32
#define NIT (ADIM/BK)     // 8
#define AS2 20            // As2[m][k2] half2 stride (16 data + 4 pad)
#define WS2 20            // Ws2[n][k2] half2 stride

// attention tiling
#define TQ 128
#define TJ 64
#define QS2 20            // Qs2[q][c2] (16 data + 4 pad)
#define KS2 20            // Ks2[j][c2]
#define VS2 36            // Vts2[c][j2] (32 data + 4 pad)
#define BSTR 68           // bias tile float stride

// Scratch (allocation-free rule: __device__ globals)
__device__ unsigned g_qh[(size_t)BDIM*NH*NQ*16];   // q packed half2 [bh][q][c2]
__device__ unsigned g_kh[(size_t)BDIM*NH*NK*16];   // k packed half2 [bh][k][c2]
__device__ float    g_v[(size_t)BDIM*NH*NK*CDIM];
__device__ float    g_gate[(size_t)BDIM*NH*NQ*CDIM];
__device__ float    g_wg[(size_t)BDIM*NQ*NH*CDIM];
__device__ unsigned g_wt[5][256][128];             // packed W^T half2: [mat][n][k2]

__device__ __forceinline__ unsigned f2h2(float x, float y)
{
    __half2 h = __floats2half2_rn(x, y);
    return *(unsigned*)&h;
}

__device__ __forceinline__ void mma_f16(float d[4], const unsigned a[4], const unsigned b[2])
{
    asm volatile(
        "mma.sync.aligned.m16n8k16.row.col.f32.f16.f16.f32 "
        "{%0,%1,%2,%3}, {%4,%5,%6,%7}, {%8,%9}, {%0,%1,%2,%3};"
        : "+f"(d[0]), "+f"(d[1]), "+f"(d[2]), "+f"(d[3])
        : "r"(a[0]), "r"(a[1]), "r"(a[2]), "r"(a[3]),
          "r"(b[0]), "r"(b[1]));
}

// ---------------------------------------------------------------------------
// Pack weights: g_wt[mat][n][k2] = half2(W[2k2][n], W[2k2+1][n])
// ---------------------------------------------------------------------------
__global__ __launch_bounds__(256) void pack_w_kernel(
    const float* __restrict__ qw, const float* __restrict__ gw,
    const float* __restrict__ kw, const float* __restrict__ vw,
    const float* __restrict__ ow)
{
    const int n  = threadIdx.x;
    const int k2 = blockIdx.x;
    const int mat = blockIdx.y;
    const float* W = (mat == 0) ? qw : (mat == 1) ? gw : (mat == 2) ? kw
                   : (mat == 3) ? vw : ow;
    float x = W[(size_t)(2 * k2) * 256 + n];
    float y = W[(size_t)(2 * k2 + 1) * 256 + n];
    g_wt[mat][n][k2] = f2h2(x, y);
}

// ---------------------------------------------------------------------------
// fp16 MMA GEMM core, double-buffered, BK=32, one sync per iteration.
// C[128x64] tile of A[MROWS,256] (fp32) x W (packed g_wt half2).
// ---------------------------------------------------------------------------
__device__ __forceinline__ void gemm_core_f16(
    const float* __restrict__ A, const unsigned* __restrict__ Wt,
    int rowBase, int nColBase, float acc[2][4][4])
{
    __shared__ unsigned As2[2][BM][AS2];
    __shared__ unsigned Ws2[2][BN][WS2];
    const int t    = threadIdx.x;
    const int lane = t & 31;
    const int wid  = t >> 5;
    const int g    = lane >> 2;
    const int tg   = lane & 3;
    const int mBase = (wid & 3) * 32;
    const int nBase = (wid >> 2) * 32;

    // A staging coords: 4 float4 per thread
    const int am  = t >> 1;              // row pair base: s = t + l*256 -> m = s>>1? no:
    (void)am;
    // s = t + l*256, l in 0..3 ; m = s>>3 (0..127), kk = (s&7)*4 (0..28)
    // W staging: one uint4 per thread: n = t>>2, k2l = (t&3)*4

#pragma unroll
    for (int mf = 0; mf < 2; mf++)
#pragma unroll
        for (int nf = 0; nf < 4; nf++)
#pragma unroll
            for (int r = 0; r < 4; r++) acc[mf][nf][r] = 0.f;

    float4 avr[4];
    uint4  wvr;
    const int wn  = t >> 2;
    const int wk4 = (t & 3) * 4;

    // prologue: load + stage tile 0
#pragma unroll
    for (int l = 0; l < 4; l++) {
        int s = t + l * 256;
        int m = s >> 3, kk = (s & 7) * 4;
        avr[l] = *(const float4*)(A + (size_t)(rowBase + m) * ADIM + 0 + kk);
    }
    wvr = *(const uint4*)(Wt + (size_t)(nColBase + wn) * 128 + 0 + wk4);
#pragma unroll
    for (int l = 0; l < 4; l++) {
        int s = t + l * 256;
        int m = s >> 3, kk = (s & 7) * 4;
        uint2 hv;
        hv.x = f2h2(avr[l].x, avr[l].y);
        hv.y = f2h2(avr[l].z, avr[l].w);
        *(uint2*)&As2[0][m][kk >> 1] = hv;
    }
    *(uint4*)&Ws2[0][wn][wk4] = wvr;
    __syncthreads();

    for (int it = 0; it < NIT; it++) {
        const int cur = it & 1;
        if (it + 1 < NIT) {
            int k0 = (it + 1) * BK;
#pragma unroll
            for (int l = 0; l < 4; l++) {
                int s = t + l * 256;
                int m = s >> 3, kk = (s & 7) * 4;
                avr[l] = *(const float4*)(A + (size_t)(rowBase + m) * ADIM + k0 + kk);
            }
            wvr = *(const uint4*)(Wt + (size_t)(nColBase + wn) * 128 + (k0 >> 1) + wk4);
        }
#pragma unroll
        for (int kc = 0; kc < 2; kc++) {
            int ks2 = kc * 8;
            unsigned a[2][4], b[4][2];
#pragma unroll
            for (int mf = 0; mf < 2; mf++) {
                int m0 = mBase + mf * 16 + g;
                a[mf][0] = As2[cur][m0    ][ks2 + tg    ];
                a[mf][1] = As2[cur][m0 + 8][ks2 + tg    ];
                a[mf][2] = As2[cur][m0    ][ks2 + tg + 4];
                a[mf][3] = As2[cur][m0 + 8][ks2 + tg + 4];
            }
#pragma unroll
            for (int nf = 0; nf < 4; nf++) {
                int n0 = nBase + nf * 8 + g;
                b[nf][0] = Ws2[cur][n0][ks2 + tg    ];
                b[nf][1] = Ws2[cur][n0][ks2 + tg + 4];
            }
#pragma unroll
            for (int mf = 0; mf < 2; mf++)
#pragma unroll
                for (int nf = 0; nf < 4; nf++)
                    mma_f16(acc[mf][nf], a[mf], b[nf]);
        }
        if (it + 1 < NIT) {
            const int nxt = (it + 1) & 1;
#pragma unroll
            for (int l = 0; l < 4; l++) {
                int s = t + l * 256;
                int m = s >> 3, kk = (s & 7) * 4;
                uint2 hv;
                hv.x = f2h2(avr[l].x, avr[l].y);
                hv.y = f2h2(avr[l].z, avr[l].w);
                *(uint2*)&As2[nxt][m][kk >> 1] = hv;
            }
            *(uint4*)&Ws2[nxt][wn][wk4] = wvr;
            __syncthreads();
        }
    }
}

// q & gate projection: grid (8, 384). cols [0,256)=q (scaled, half2 out), [256,512)=gate
__global__ __launch_bounds__(256) void proj_qg_kernel(
    const float* __restrict__ qdata, const float* __restrict__ gating_b)
{
    const int rowBase = blockIdx.y * BM;
    const int n0 = blockIdx.x * BN;
    const bool isGate = (n0 >= 256);
    const unsigned* Wt = isGate ? &g_wt[1][0][0] : &g_wt[0][0][0];
    const int nColBase = isGate ? (n0 - 256) : n0;

    float acc[2][4][4];
    gemm_core_f16(qdata, Wt, rowBase, nColBase, acc);

    const float scale = 0.17677669529663687f; // 1/sqrt(32)
    const int t = threadIdx.x, lane = t & 31, wid = t >> 5;
    const int g = lane >> 2, tg = lane & 3;
    const int mBase = (wid & 3) * 32, nBase = (wid >> 2) * 32;
#pragma unroll
    for (int mf = 0; mf < 2; mf++)
#pragma unroll
        for (int nf = 0; nf < 4; nf++) {
            int nPair = nColBase + nBase + nf * 8 + tg * 2;   // even col
            int h  = nPair >> 5;
            int c2 = (nPair & 31) >> 1;
            int row0 = rowBase + mBase + mf * 16 + g;
            int row1 = row0 + 8;
            int b = row0 / NQ;
            int qi0 = row0 % NQ, qi1 = row1 % NQ;
            if (!isGate) {
                g_qh[((size_t)(b * NH + h) * NQ + qi0) * 16 + c2] =
                    f2h2(acc[mf][nf][0] * scale, acc[mf][nf][1] * scale);
                g_qh[((size_t)(b * NH + h) * NQ + qi1) * 16 + c2] =
                    f2h2(acc[mf][nf][2] * scale, acc[mf][nf][3] * scale);
            } else {
                float gb0 = gating_b[nPair], gb1 = gating_b[nPair + 1];
                size_t i0 = ((size_t)(b * NH + h) * NQ + qi0) * CDIM + (nPair & 31);
                size_t i1 = ((size_t)(b * NH + h) * NQ + qi1) * CDIM + (nPair & 31);
                g_gate[i0    ] = 1.f / (1.f + __expf(-(acc[mf][nf][0] + gb0)));
                g_gate[i0 + 1] = 1.f / (1.f + __expf(-(acc[mf][nf][1] + gb1)));
                g_gate[i1    ] = 1.f / (1.f + __expf(-(acc[mf][nf][2] + gb0)));
                g_gate[i1 + 1] = 1.f / (1.f + __expf(-(acc[mf][nf][3] + gb1)));
            }
        }
}

// k & v projection: grid (8, 384). cols [0,256)=k (half2 out), [256,512)=v (fp32)
__global__ __launch_bounds__(256) void proj_kv_kernel(
    const float* __restrict__ mdata)
{
    const int rowBase = blockIdx.y * BM;
    const int n0 = blockIdx.x * BN;
    const bool isV = (n0 >= 256);
    const unsigned* Wt = isV ? &g_wt[3][0][0] : &g_wt[2][0][0];
    const int nColBase = isV ? (n0 - 256) : n0;

    float acc[2][4][4];
    gemm_core_f16(mdata, Wt, rowBase, nColBase, acc);

    const int t = threadIdx.x, lane = t & 31, wid = t >> 5;
    const int g = lane >> 2, tg = lane & 3;
    const int mBase = (wid & 3) * 32, nBase = (wid >> 2) * 32;
#pragma unroll
    for (int mf = 0; mf < 2; mf++)
#pragma unroll
        for (int nf = 0; nf < 4; nf++) {
            int nPair = nColBase + nBase + nf * 8 + tg * 2;
            int h  = nPair >> 5;
            int c2 = (nPair & 31) >> 1;
            int row0 = rowBase + mBase + mf * 16 + g;
            int row1 = row0 + 8;
            int b = row0 / NK;
            int ki0 = row0 % NK, ki1 = row1 % NK;
            if (!isV) {
                g_kh[((size_t)(b * NH + h) * NK + ki0) * 16 + c2] =
                    f2h2(acc[mf][nf][0], acc[mf][nf][1]);
                g_kh[((size_t)(b * NH + h) * NK + ki1) * 16 + c2] =
                    f2h2(acc[mf][nf][2], acc[mf][nf][3]);
            } else {
                size_t i0 = ((size_t)(b * NH + h) * NK + ki0) * CDIM + (nPair & 31);
                size_t i1 = ((size_t)(b * NH + h) * NK + ki1) * CDIM + (nPair & 31);
                g_v[i0    ] = acc[mf][nf][0];
                g_v[i0 + 1] = acc[mf][nf][1];
                g_v[i1    ] = acc[mf][nf][2];
                g_v[i1 + 1] = acc[mf][nf][3];
            }
        }
}

// ---------------------------------------------------------------------------
// fp16 tensor-core flash attention, P kept in registers (S c-frag == PV a-frag).
// grid (NQ/TQ, BDIM*NH), 256 threads; warp w owns q-rows [16w,16w+16).
// ---------------------------------------------------------------------------
__global__ void __launch_bounds__(256, 2) attn_mma_kernel(
    const float* __restrict__ bias, const float* __restrict__ nb)
{
    const int qt = blockIdx.x;
    const int bh = blockIdx.y;
    const int b = bh >> 3, h = bh & 7;
    const int qBase = qt * TQ;

    extern __shared__ float sh[];
    unsigned* Qs2  = (unsigned*)sh;          // [128][QS2]
    unsigned* Ks2  = Qs2 + TQ * QS2;         // [64][KS2]
    unsigned* Vts2 = Ks2 + TJ * KS2;         // [32][VS2]
    float*    bsh  = (float*)(Vts2 + CDIM * VS2); // [128][BSTR]

    const int tid  = threadIdx.x;
    const int lane = tid & 31, wid = tid >> 5;
    const int g = lane >> 2, tg = lane & 3;
    const int m0 = wid * 16;

    // ---- stage Q tile (already packed half2) ----
    const uint4* qg4 = (const uint4*)(g_qh + ((size_t)bh * NQ + qBase) * 16);
#pragma unroll
    for (int l = 0; l < 2; l++) {
        int s = tid + l * 256;           // uint4 slot (128 rows x 4)
        int r = s >> 2, q4 = s & 3;
        *(uint4*)&Qs2[r * QS2 + q4 * 4] = qg4[r * 4 + q4];
    }
    __syncthreads();

    unsigned qa[2][4];
#pragma unroll
    for (int kc = 0; kc < 2; kc++) {
        int ks2 = kc * 8;
        qa[kc][0] = Qs2[(m0 + g    ) * QS2 + ks2 + tg    ];
        qa[kc][1] = Qs2[(m0 + g + 8) * QS2 + ks2 + tg    ];
        qa[kc][2] = Qs2[(m0 + g    ) * QS2 + ks2 + tg + 4];
        qa[kc][3] = Qs2[(m0 + g + 8) * QS2 + ks2 + tg + 4];
    }

    float oacc[4][4];
#pragma unroll
    for (int nf = 0; nf < 4; nf++)
#pragma unroll
        for (int r = 0; r < 4; r++) oacc[nf][r] = 0.f;
    float mrow0 = -1e30f, mrow1 = -1e30f, lrow0 = 0.f, lrow1 = 0.f;

    const unsigned* kgp = g_kh + (size_t)bh * NK * 16;
    const float* vgp = g_v + (size_t)bh * NK * CDIM;
    const float* bgp = bias + ((size_t)b * NQ + qBase) * NK;
    const float* ngp = nb + (size_t)qBase * NK;

    for (int jt = 0; jt < NK; jt += TJ) {
        __syncthreads();   // prior tile fully consumed
        // K tile: 64 rows x 4 uint4, one per thread
        {
            int r = tid >> 2, q4 = tid & 3;
            *(uint4*)&Ks2[r * KS2 + q4 * 4] =
                *(const uint4*)(kgp + ((size_t)(jt + r)) * 16 + q4 * 4);
        }
        // V tile [64][32] fp32 -> Vts2 [c][j2] transposed half2
        {
            int r2 = tid >> 3;           // j-pair 0..31
            int c4 = (tid & 7) * 4;
            float4 v0 = *(const float4*)(vgp + (size_t)(jt + 2 * r2    ) * CDIM + c4);
            float4 v1 = *(const float4*)(vgp + (size_t)(jt + 2 * r2 + 1) * CDIM + c4);
            Vts2[(c4 + 0) * VS2 + r2] = f2h2(v0.x, v1.x);
            Vts2[(c4 + 1) * VS2 + r2] = f2h2(v0.y, v1.y);
            Vts2[(c4 + 2) * VS2 + r2] = f2h2(v0.z, v1.z);
            Vts2[(c4 + 3) * VS2 + r2] = f2h2(v0.w, v1.w);
        }
        // bias tile [128 q][64 j] (+ nonbatched) fp32 -> bsh via STS.128
#pragma unroll
        for (int l = 0; l < 8; l++) {
            int s = tid + l * 256;
            int r = s >> 4, c4 = (s & 15) * 4;
            float4 bv = *(const float4*)(bgp + (size_t)r * NK + jt + c4);
            float4 nv = *(const float4*)(ngp + (size_t)r * NK + jt + c4);
            float4 sum4;
            sum4.x = bv.x + nv.x; sum4.y = bv.y + nv.y;
            sum4.z = bv.z + nv.z; sum4.w = bv.w + nv.w;
            *(float4*)&bsh[r * BSTR + c4] = sum4;
        }
        __syncthreads();

        // S = Q K^T : sf[8 nf][4]
        float sf[8][4];
#pragma unroll
        for (int nf = 0; nf < 8; nf++)
#pragma unroll
            for (int r = 0; r < 4; r++) sf[nf][r] = 0.f;
#pragma unroll
        for (int kc = 0; kc < 2; kc++) {
            int ks2 = kc * 8;
            unsigned bf[8][2];
#pragma unroll
            for (int nf = 0; nf < 8; nf++) {
                bf[nf][0] = Ks2[(nf * 8 + g) * KS2 + ks2 + tg    ];
                bf[nf][1] = Ks2[(nf * 8 + g) * KS2 + ks2 + tg + 4];
            }
#pragma unroll
            for (int nf = 0; nf < 8; nf++)
                mma_f16(sf[nf], qa[kc], bf[nf]);
        }
        // + bias
#pragma unroll
        for (int nf = 0; nf < 8; nf++) {
            float2 b01 = *(const float2*)&bsh[(m0 + g    ) * BSTR + nf * 8 + 2 * tg];
            float2 b23 = *(const float2*)&bsh[(m0 + g + 8) * BSTR + nf * 8 + 2 * tg];
            sf[nf][0] += b01.x; sf[nf][1] += b01.y;
            sf[nf][2] += b23.x; sf[nf][3] += b23.y;
        }
        // row maxima
        float mx0 = -1e30f, mx1 = -1e30f;
#pragma unroll
        for (int nf = 0; nf < 8; nf++) {
            mx0 = fmaxf(mx0, fmaxf(sf[nf][0], sf[nf][1]));
            mx1 = fmaxf(mx1, fmaxf(sf[nf][2], sf[nf][3]));
        }
        mx0 = fmaxf(mx0, __shfl_xor_sync(0xffffffffu, mx0, 1));
        mx0 = fmaxf(mx0, __shfl_xor_sync(0xffffffffu, mx0, 2));
        mx1 = fmaxf(mx1, __shfl_xor_sync(0xffffffffu, mx1, 1));
        mx1 = fmaxf(mx1, __shfl_xor_sync(0xffffffffu, mx1, 2));
        float mn0 = fmaxf(mrow0, mx0), mn1 = fmaxf(mrow1, mx1);
        float cor0 = __expf(mrow0 - mn0), cor1 = __expf(mrow1 - mn1);
        mrow0 = mn0; mrow1 = mn1;
        lrow0 *= cor0; lrow1 *= cor1;
#pragma unroll
        for (int nf = 0; nf < 4; nf++) {
            oacc[nf][0] *= cor0; oacc[nf][1] *= cor0;
            oacc[nf][2] *= cor1; oacc[nf][3] *= cor1;
        }
        // p = exp(s-m) in place; accumulate row sums
        float s0 = 0.f, s1 = 0.f;
#pragma unroll
        for (int nf = 0; nf < 8; nf++) {
            sf[nf][0] = __expf(sf[nf][0] - mn0);
            sf[nf][1] = __expf(sf[nf][1] - mn0);
            sf[nf][2] = __expf(sf[nf][2] - mn1);
            sf[nf][3] = __expf(sf[nf][3] - mn1);
            s0 += sf[nf][0] + sf[nf][1];
            s1 += sf[nf][2] + sf[nf][3];
        }
        s0 += __shfl_xor_sync(0xffffffffu, s0, 1);
        s0 += __shfl_xor_sync(0xffffffffu, s0, 2);
        s1 += __shfl_xor_sync(0xffffffffu, s1, 1);
        s1 += __shfl_xor_sync(0xffffffffu, s1, 2);
        lrow0 += s0; lrow1 += s1;

        // O += P V  — P fragments straight from sf registers
#pragma unroll
        for (int kc = 0; kc < 4; kc++) {
            int ks2 = kc * 8;
            unsigned pa[4];
            pa[0] = f2h2(sf[2 * kc    ][0], sf[2 * kc    ][1]);
            pa[1] = f2h2(sf[2 * kc    ][2], sf[2 * kc    ][3]);
            pa[2] = f2h2(sf[2 * kc + 1][0], sf[2 * kc + 1][1]);
            pa[3] = f2h2(sf[2 * kc + 1][2], sf[2 * kc + 1][3]);
            unsigned vb[4][2];
#pragma unroll
            for (int nf = 0; nf < 4; nf++) {
                vb[nf][0] = Vts2[(nf * 8 + g) * VS2 + ks2 + tg    ];
                vb[nf][1] = Vts2[(nf * 8 + g) * VS2 + ks2 + tg + 4];
            }
#pragma unroll
            for (int nf = 0; nf < 4; nf++)
                mma_f16(oacc[nf], pa, vb[nf]);
        }
    }

    // epilogue: normalize, gate, write g_wg
    float inv0 = 1.f / lrow0, inv1 = 1.f / lrow1;
    int r0 = qBase + m0 + g, r1 = r0 + 8;
    const float* gate0 = g_gate + ((size_t)bh * NQ + r0) * CDIM;
    const float* gate1 = g_gate + ((size_t)bh * NQ + r1) * CDIM;
    float* w0 = g_wg + (((size_t)b * NQ + r0) * NH + h) * CDIM;
    float* w1 = g_wg + (((size_t)b * NQ + r1) * NH + h) * CDIM;
#pragma unroll
    for (int nf = 0; nf < 4; nf++) {
        int c = nf * 8 + 2 * tg;
        float2 ga = *(const float2*)(gate0 + c);
        float2 gb = *(const float2*)(gate1 + c);
        float2 oa, ob;
        oa.x = oacc[nf][0] * inv0 * ga.x;
        oa.y = oacc[nf][1] * inv0 * ga.y;
        ob.x = oacc[nf][2] * inv1 * gb.x;
        ob.y = oacc[nf][3] * inv1 * gb.y;
        *(float2*)(w0 + c) = oa;
        *(float2*)(w1 + c) = ob;
    }
}

// Output projection: wg[49152,256] x output_w[256,256] + output_b. grid (4,384)
__global__ __launch_bounds__(256) void out_kernel(
    const float* __restrict__ output_b, float* __restrict__ out)
{
    const int rowBase = blockIdx.y * BM;
    const int n0 = blockIdx.x * BN;
    float acc[2][4][4];
    gemm_core_f16(g_wg, &g_wt[4][0][0], rowBase, n0, acc);

    const int t = threadIdx.x, lane = t & 31, wid = t >> 5;
    const int g = lane >> 2, tg = lane & 3;
    const int mBase = (wid & 3) * 32, nBase = (wid >> 2) * 32;
#pragma unroll
    for (int mf = 0; mf < 2; mf++)
#pragma unroll
        for (int nf = 0; nf < 4; nf++)
#pragma unroll
            for (int r = 0; r < 4; r++) {
                int row = rowBase + mBase + mf * 16 + ((r & 2) ? 8 : 0) + g;
                int n   = n0 + nBase + nf * 8 + tg * 2 + (r & 1);
                out[(size_t)row * ODIM + n] = acc[mf][nf][r] + output_b[n];
            }
}

extern "C" void kernel_launch(void* const* d_in, const int* in_sizes, int n_in,
                              void* d_out, int out_size)
{
    const float* q_data   = (const float*)d_in[0];
    const float* m_data   = (const float*)d_in[1];
    const float* bias     = (const float*)d_in[2];
    const float* nbias    = (const float*)d_in[3];
    const float* query_w  = (const float*)d_in[4];
    const float* key_w    = (const float*)d_in[5];
    const float* value_w  = (const float*)d_in[6];
    const float* gating_w = (const float*)d_in[7];
    const float* gating_b = (const float*)d_in[8];
    const float* output_w = (const float*)d_in[9];
    const float* output_b = (const float*)d_in[10];
    float* out = (float*)d_out;

    const int smem_attn = (TQ * QS2 + TJ * KS2 + CDIM * VS2) * 4
                          + TQ * BSTR * 4;   // ~53.5 KB
    cudaFuncSetAttribute(attn_mma_kernel, cudaFuncAttributeMaxDynamicSharedMemorySize, smem_attn);

    dim3 gpack(128, 5);
    pack_w_kernel<<<gpack, 256>>>(query_w, gating_w, key_w, value_w, output_w);

    dim3 gproj(8, MROWS / BM);
    proj_qg_kernel<<<gproj, 256>>>(q_data, gating_b);
    proj_kv_kernel<<<gproj, 256>>>(m_data);
    dim3 gattn(NQ / TQ, BDIM * NH);
    attn_mma_kernel<<<gattn, 256, smem_attn>>>(bias, nbias);
    dim3 gout(4, MROWS / BM);
    out_kernel<<<gout, 256>>>(output_b, out);
}

// round 8
// speedup vs baseline: 5.6002x; 1.0408x over previous
#include <cuda_runtime.h>
#include <cuda_fp16.h>
#include <math.h>

#define BDIM 128
#define NQ 384
#define NK 384
#define NH 8
#define CDIM 32
#define ADIM 256
#define ODIM 256
#define MROWS (BDIM*NQ)   // 49152

#define BM 128
#define BN 64
#define BK 32
#define NIT (ADIM/BK)     // 8
#define AS2 20            // As2[m][k2] half2 stride
#define WS2 20            // Ws2[n][k2] half2 stride

// attention tiling
#define TQ 128
#define TJ 64
#define QS2 20            // Qs2[q][c2]
#define KS2 20            // Ks2[j][c2]  (also V)
#define BSTR 68           // bias tile float stride

// Scratch (allocation-free rule: __device__ globals)
__device__ unsigned g_qh[(size_t)BDIM*NH*NQ*16];   // q packed half2 [bh][q][c2]
__device__ unsigned g_kh[(size_t)BDIM*NH*NK*16];   // k packed half2 [bh][k][c2]
__device__ unsigned g_vh[(size_t)BDIM*NH*NK*16];   // v packed half2 [bh][k][c2]
__device__ float    g_gate[(size_t)BDIM*NH*NQ*CDIM];
__device__ float    g_wg[(size_t)BDIM*NQ*NH*CDIM];
__device__ unsigned g_wt[5][256][128];             // packed W^T half2: [mat][n][k2]

__device__ __forceinline__ unsigned f2h2(float x, float y)
{
    __half2 h = __floats2half2_rn(x, y);
    return *(unsigned*)&h;
}

__device__ __forceinline__ void mma_f16(float d[4], const unsigned a[4], const unsigned b[2])
{
    asm volatile(
        "mma.sync.aligned.m16n8k16.row.col.f32.f16.f16.f32 "
        "{%0,%1,%2,%3}, {%4,%5,%6,%7}, {%8,%9}, {%0,%1,%2,%3};"
        : "+f"(d[0]), "+f"(d[1]), "+f"(d[2]), "+f"(d[3])
        : "r"(a[0]), "r"(a[1]), "r"(a[2]), "r"(a[3]),
          "r"(b[0]), "r"(b[1]));
}

__device__ __forceinline__ void ldsm_x4(unsigned r[4], unsigned addr)
{
    asm volatile("ldmatrix.sync.aligned.m8n8.x4.shared.b16 {%0,%1,%2,%3}, [%4];"
                 : "=r"(r[0]), "=r"(r[1]), "=r"(r[2]), "=r"(r[3]) : "r"(addr));
}

__device__ __forceinline__ void ldsm_x4_trans(unsigned r[4], unsigned addr)
{
    asm volatile("ldmatrix.sync.aligned.m8n8.x4.trans.shared.b16 {%0,%1,%2,%3}, [%4];"
                 : "=r"(r[0]), "=r"(r[1]), "=r"(r[2]), "=r"(r[3]) : "r"(addr));
}

// ---------------------------------------------------------------------------
// Pack weights: g_wt[mat][n][k2] = half2(W[2k2][n], W[2k2+1][n])
// ---------------------------------------------------------------------------
__global__ __launch_bounds__(256) void pack_w_kernel(
    const float* __restrict__ qw, const float* __restrict__ gw,
    const float* __restrict__ kw, const float* __restrict__ vw,
    const float* __restrict__ ow)
{
    const int n  = threadIdx.x;
    const int k2 = blockIdx.x;
    const int mat = blockIdx.y;
    const float* W = (mat == 0) ? qw : (mat == 1) ? gw : (mat == 2) ? kw
                   : (mat == 3) ? vw : ow;
    float x = W[(size_t)(2 * k2) * 256 + n];
    float y = W[(size_t)(2 * k2 + 1) * 256 + n];
    g_wt[mat][n][k2] = f2h2(x, y);
}

// ---------------------------------------------------------------------------
// fp16 MMA GEMM core, double-buffered, BK=32, one sync per iteration.
// ---------------------------------------------------------------------------
__device__ __forceinline__ void gemm_core_f16(
    const float* __restrict__ A, const unsigned* __restrict__ Wt,
    int rowBase, int nColBase, float acc[2][4][4])
{
    __shared__ unsigned As2[2][BM][AS2];
    __shared__ unsigned Ws2[2][BN][WS2];
    const int t    = threadIdx.x;
    const int lane = t & 31;
    const int wid  = t >> 5;
    const int g    = lane >> 2;
    const int tg   = lane & 3;
    const int mBase = (wid & 3) * 32;
    const int nBase = (wid >> 2) * 32;

#pragma unroll
    for (int mf = 0; mf < 2; mf++)
#pragma unroll
        for (int nf = 0; nf < 4; nf++)
#pragma unroll
            for (int r = 0; r < 4; r++) acc[mf][nf][r] = 0.f;

    float4 avr[4];
    uint4  wvr;
    const int wn  = t >> 2;
    const int wk4 = (t & 3) * 4;

#pragma unroll
    for (int l = 0; l < 4; l++) {
        int s = t + l * 256;
        int m = s >> 3, kk = (s & 7) * 4;
        avr[l] = *(const float4*)(A + (size_t)(rowBase + m) * ADIM + 0 + kk);
    }
    wvr = *(const uint4*)(Wt + (size_t)(nColBase + wn) * 128 + 0 + wk4);
#pragma unroll
    for (int l = 0; l < 4; l++) {
        int s = t + l * 256;
        int m = s >> 3, kk = (s & 7) * 4;
        uint2 hv;
        hv.x = f2h2(avr[l].x, avr[l].y);
        hv.y = f2h2(avr[l].z, avr[l].w);
        *(uint2*)&As2[0][m][kk >> 1] = hv;
    }
    *(uint4*)&Ws2[0][wn][wk4] = wvr;
    __syncthreads();

    for (int it = 0; it < NIT; it++) {
        const int cur = it & 1;
        if (it + 1 < NIT) {
            int k0 = (it + 1) * BK;
#pragma unroll
            for (int l = 0; l < 4; l++) {
                int s = t + l * 256;
                int m = s >> 3, kk = (s & 7) * 4;
                avr[l] = *(const float4*)(A + (size_t)(rowBase + m) * ADIM + k0 + kk);
            }
            wvr = *(const uint4*)(Wt + (size_t)(nColBase + wn) * 128 + (k0 >> 1) + wk4);
        }
#pragma unroll
        for (int kc = 0; kc < 2; kc++) {
            int ks2 = kc * 8;
            unsigned a[2][4], b[4][2];
#pragma unroll
            for (int mf = 0; mf < 2; mf++) {
                int m0 = mBase + mf * 16 + g;
                a[mf][0] = As2[cur][m0    ][ks2 + tg    ];
                a[mf][1] = As2[cur][m0 + 8][ks2 + tg    ];
                a[mf][2] = As2[cur][m0    ][ks2 + tg + 4];
                a[mf][3] = As2[cur][m0 + 8][ks2 + tg + 4];
            }
#pragma unroll
            for (int nf = 0; nf < 4; nf++) {
                int n0 = nBase + nf * 8 + g;
                b[nf][0] = Ws2[cur][n0][ks2 + tg    ];
                b[nf][1] = Ws2[cur][n0][ks2 + tg + 4];
            }
#pragma unroll
            for (int mf = 0; mf < 2; mf++)
#pragma unroll
                for (int nf = 0; nf < 4; nf++)
                    mma_f16(acc[mf][nf], a[mf], b[nf]);
        }
        if (it + 1 < NIT) {
            const int nxt = (it + 1) & 1;
#pragma unroll
            for (int l = 0; l < 4; l++) {
                int s = t + l * 256;
                int m = s >> 3, kk = (s & 7) * 4;
                uint2 hv;
                hv.x = f2h2(avr[l].x, avr[l].y);
                hv.y = f2h2(avr[l].z, avr[l].w);
                *(uint2*)&As2[nxt][m][kk >> 1] = hv;
            }
            *(uint4*)&Ws2[nxt][wn][wk4] = wvr;
            __syncthreads();
        }
    }
}

// q & gate projection: grid (8, 384). cols [0,256)=q (scaled, half2), [256,512)=gate
__global__ __launch_bounds__(256) void proj_qg_kernel(
    const float* __restrict__ qdata, const float* __restrict__ gating_b)
{
    const int rowBase = blockIdx.y * BM;
    const int n0 = blockIdx.x * BN;
    const bool isGate = (n0 >= 256);
    const unsigned* Wt = isGate ? &g_wt[1][0][0] : &g_wt[0][0][0];
    const int nColBase = isGate ? (n0 - 256) : n0;

    float acc[2][4][4];
    gemm_core_f16(qdata, Wt, rowBase, nColBase, acc);

    const float scale = 0.17677669529663687f; // 1/sqrt(32)
    const int t = threadIdx.x, lane = t & 31, wid = t >> 5;
    const int g = lane >> 2, tg = lane & 3;
    const int mBase = (wid & 3) * 32, nBase = (wid >> 2) * 32;
#pragma unroll
    for (int mf = 0; mf < 2; mf++)
#pragma unroll
        for (int nf = 0; nf < 4; nf++) {
            int nPair = nColBase + nBase + nf * 8 + tg * 2;
            int h  = nPair >> 5;
            int c2 = (nPair & 31) >> 1;
            int row0 = rowBase + mBase + mf * 16 + g;
            int row1 = row0 + 8;
            int b = row0 / NQ;
            int qi0 = row0 % NQ, qi1 = row1 % NQ;
            if (!isGate) {
                g_qh[((size_t)(b * NH + h) * NQ + qi0) * 16 + c2] =
                    f2h2(acc[mf][nf][0] * scale, acc[mf][nf][1] * scale);
                g_qh[((size_t)(b * NH + h) * NQ + qi1) * 16 + c2] =
                    f2h2(acc[mf][nf][2] * scale, acc[mf][nf][3] * scale);
            } else {
                float gb0 = gating_b[nPair], gb1 = gating_b[nPair + 1];
                size_t i0 = ((size_t)(b * NH + h) * NQ + qi0) * CDIM + (nPair & 31);
                size_t i1 = ((size_t)(b * NH + h) * NQ + qi1) * CDIM + (nPair & 31);
                g_gate[i0    ] = 1.f / (1.f + __expf(-(acc[mf][nf][0] + gb0)));
                g_gate[i0 + 1] = 1.f / (1.f + __expf(-(acc[mf][nf][1] + gb1)));
                g_gate[i1    ] = 1.f / (1.f + __expf(-(acc[mf][nf][2] + gb0)));
                g_gate[i1 + 1] = 1.f / (1.f + __expf(-(acc[mf][nf][3] + gb1)));
            }
        }
}

// k & v projection: grid (8, 384). cols [0,256)=k, [256,512)=v — both packed half2
__global__ __launch_bounds__(256) void proj_kv_kernel(
    const float* __restrict__ mdata)
{
    const int rowBase = blockIdx.y * BM;
    const int n0 = blockIdx.x * BN;
    const bool isV = (n0 >= 256);
    const unsigned* Wt = isV ? &g_wt[3][0][0] : &g_wt[2][0][0];
    const int nColBase = isV ? (n0 - 256) : n0;

    float acc[2][4][4];
    gemm_core_f16(mdata, Wt, rowBase, nColBase, acc);

    unsigned* dst = isV ? g_vh : g_kh;
    const int t = threadIdx.x, lane = t & 31, wid = t >> 5;
    const int g = lane >> 2, tg = lane & 3;
    const int mBase = (wid & 3) * 32, nBase = (wid >> 2) * 32;
#pragma unroll
    for (int mf = 0; mf < 2; mf++)
#pragma unroll
        for (int nf = 0; nf < 4; nf++) {
            int nPair = nColBase + nBase + nf * 8 + tg * 2;
            int h  = nPair >> 5;
            int c2 = (nPair & 31) >> 1;
            int row0 = rowBase + mBase + mf * 16 + g;
            int row1 = row0 + 8;
            int b = row0 / NK;
            int ki0 = row0 % NK, ki1 = row1 % NK;
            dst[((size_t)(b * NH + h) * NK + ki0) * 16 + c2] =
                f2h2(acc[mf][nf][0], acc[mf][nf][1]);
            dst[((size_t)(b * NH + h) * NK + ki1) * 16 + c2] =
                f2h2(acc[mf][nf][2], acc[mf][nf][3]);
        }
}

// ---------------------------------------------------------------------------
// fp16 flash attention: 128 threads / 4 warps; warp owns 32 q-rows (mf=2).
// K,V staged as row-major half2; QK B-frags ldmatrix.x4; PV B-frags
// ldmatrix.x4.trans. P stays in registers.
// ---------------------------------------------------------------------------
__global__ void __launch_bounds__(128, 3) attn_mma_kernel(
    const float* __restrict__ bias, const float* __restrict__ nb)
{
    const int qt = blockIdx.x;
    const int bh = blockIdx.y;
    const int b = bh >> 3, h = bh & 7;
    const int qBase = qt * TQ;

    extern __shared__ float sh[];
    unsigned* Qs2 = (unsigned*)sh;               // [128][QS2]
    unsigned* Ks2 = Qs2 + TQ * QS2;              // [64][KS2]
    unsigned* Vs2 = Ks2 + TJ * KS2;              // [64][KS2]
    float*    bsh = (float*)(Vs2 + TJ * KS2);    // [128][BSTR]

    const int tid  = threadIdx.x;
    const int lane = tid & 31, wid = tid >> 5;
    const int g = lane >> 2, tg = lane & 3;
    const int m0 = wid * 32;

    // ---- stage Q tile (packed half2) ----
    const uint4* qg4 = (const uint4*)(g_qh + ((size_t)bh * NQ + qBase) * 16);
#pragma unroll
    for (int l = 0; l < 4; l++) {
        int s = tid + l * 128;
        int r = s >> 2, q4 = s & 3;
        *(uint4*)&Qs2[r * QS2 + q4 * 4] = qg4[r * 4 + q4];
    }
    __syncthreads();

    unsigned qa[2][2][4];   // [mf][kc][4]
#pragma unroll
    for (int mf = 0; mf < 2; mf++)
#pragma unroll
        for (int kc = 0; kc < 2; kc++) {
            int ks2 = kc * 8;
            int r = m0 + mf * 16 + g;
            qa[mf][kc][0] = Qs2[(r    ) * QS2 + ks2 + tg    ];
            qa[mf][kc][1] = Qs2[(r + 8) * QS2 + ks2 + tg    ];
            qa[mf][kc][2] = Qs2[(r    ) * QS2 + ks2 + tg + 4];
            qa[mf][kc][3] = Qs2[(r + 8) * QS2 + ks2 + tg + 4];
        }

    float oacc[2][4][4];
#pragma unroll
    for (int mf = 0; mf < 2; mf++)
#pragma unroll
        for (int nf = 0; nf < 4; nf++)
#pragma unroll
            for (int r = 0; r < 4; r++) oacc[mf][nf][r] = 0.f;
    float mrow[2][2] = {{-1e30f, -1e30f}, {-1e30f, -1e30f}};
    float lrow[2][2] = {{0.f, 0.f}, {0.f, 0.f}};

    const unsigned* kgp = g_kh + (size_t)bh * NK * 16;
    const unsigned* vgp = g_vh + (size_t)bh * NK * 16;
    const float* bgp = bias + ((size_t)b * NQ + qBase) * NK;
    const float* ngp = nb + (size_t)qBase * NK;

    // ldmatrix base addresses (lane-dependent), computed once
    const unsigned ks_base = (unsigned)__cvta_generic_to_shared(Ks2);
    const unsigned vs_base = (unsigned)__cvta_generic_to_shared(Vs2);
    const int ltile = lane >> 3, lrowi = lane & 7;

    for (int jt = 0; jt < NK; jt += TJ) {
        __syncthreads();   // prior tile consumed
        // K + V tiles: 64 rows x 4 uint4 each, 2 per thread per tensor
#pragma unroll
        for (int l = 0; l < 2; l++) {
            int s = tid + l * 128;
            int r = s >> 2, q4 = s & 3;
            *(uint4*)&Ks2[r * KS2 + q4 * 4] =
                *(const uint4*)(kgp + ((size_t)(jt + r)) * 16 + q4 * 4);
            *(uint4*)&Vs2[r * KS2 + q4 * 4] =
                *(const uint4*)(vgp + ((size_t)(jt + r)) * 16 + q4 * 4);
        }
        // bias tile [128 q][64 j] (+ nonbatched) fp32 -> bsh
#pragma unroll
        for (int l = 0; l < 16; l++) {
            int s = tid + l * 128;
            int r = s >> 4, c4 = (s & 15) * 4;
            float4 bv = *(const float4*)(bgp + (size_t)r * NK + jt + c4);
            float4 nv = *(const float4*)(ngp + (size_t)r * NK + jt + c4);
            float4 sum4;
            sum4.x = bv.x + nv.x; sum4.y = bv.y + nv.y;
            sum4.z = bv.z + nv.z; sum4.w = bv.w + nv.w;
            *(float4*)&bsh[r * BSTR + c4] = sum4;
        }
        __syncthreads();

        // S = Q K^T : sf[mf][8 nf][4]
        float sf[2][8][4];
#pragma unroll
        for (int mf = 0; mf < 2; mf++)
#pragma unroll
            for (int nf = 0; nf < 8; nf++)
#pragma unroll
                for (int r = 0; r < 4; r++) sf[mf][nf][r] = 0.f;

#pragma unroll
        for (int kc = 0; kc < 2; kc++) {
#pragma unroll
            for (int p = 0; p < 4; p++) {
                // B frags for nf=2p, 2p+1 via ldmatrix.x4 (non-trans)
                int jrow = p * 16 + ((ltile >= 2) ? 8 : 0) + lrowi;
                int cu   = kc * 8 + (ltile & 1) * 4;
                unsigned bf[4];
                ldsm_x4(bf, ks_base + (unsigned)((jrow * KS2 + cu) * 4));
#pragma unroll
                for (int mf = 0; mf < 2; mf++) {
                    mma_f16(sf[mf][2 * p    ], qa[mf][kc], &bf[0]);
                    mma_f16(sf[mf][2 * p + 1], qa[mf][kc], &bf[2]);
                }
            }
        }

        // + bias, softmax per mf
#pragma unroll
        for (int mf = 0; mf < 2; mf++) {
            int r0 = m0 + mf * 16 + g;
#pragma unroll
            for (int nf = 0; nf < 8; nf++) {
                float2 b01 = *(const float2*)&bsh[(r0    ) * BSTR + nf * 8 + 2 * tg];
                float2 b23 = *(const float2*)&bsh[(r0 + 8) * BSTR + nf * 8 + 2 * tg];
                sf[mf][nf][0] += b01.x; sf[mf][nf][1] += b01.y;
                sf[mf][nf][2] += b23.x; sf[mf][nf][3] += b23.y;
            }
            float mx0 = -1e30f, mx1 = -1e30f;
#pragma unroll
            for (int nf = 0; nf < 8; nf++) {
                mx0 = fmaxf(mx0, fmaxf(sf[mf][nf][0], sf[mf][nf][1]));
                mx1 = fmaxf(mx1, fmaxf(sf[mf][nf][2], sf[mf][nf][3]));
            }
            mx0 = fmaxf(mx0, __shfl_xor_sync(0xffffffffu, mx0, 1));
            mx0 = fmaxf(mx0, __shfl_xor_sync(0xffffffffu, mx0, 2));
            mx1 = fmaxf(mx1, __shfl_xor_sync(0xffffffffu, mx1, 1));
            mx1 = fmaxf(mx1, __shfl_xor_sync(0xffffffffu, mx1, 2));
            float mn0 = fmaxf(mrow[mf][0], mx0), mn1 = fmaxf(mrow[mf][1], mx1);
            float cor0 = __expf(mrow[mf][0] - mn0), cor1 = __expf(mrow[mf][1] - mn1);
            mrow[mf][0] = mn0; mrow[mf][1] = mn1;
            lrow[mf][0] *= cor0; lrow[mf][1] *= cor1;
#pragma unroll
            for (int nf = 0; nf < 4; nf++) {
                oacc[mf][nf][0] *= cor0; oacc[mf][nf][1] *= cor0;
                oacc[mf][nf][2] *= cor1; oacc[mf][nf][3] *= cor1;
            }
            float s0 = 0.f, s1 = 0.f;
#pragma unroll
            for (int nf = 0; nf < 8; nf++) {
                sf[mf][nf][0] = __expf(sf[mf][nf][0] - mn0);
                sf[mf][nf][1] = __expf(sf[mf][nf][1] - mn0);
                sf[mf][nf][2] = __expf(sf[mf][nf][2] - mn1);
                sf[mf][nf][3] = __expf(sf[mf][nf][3] - mn1);
                s0 += sf[mf][nf][0] + sf[mf][nf][1];
                s1 += sf[mf][nf][2] + sf[mf][nf][3];
            }
            s0 += __shfl_xor_sync(0xffffffffu, s0, 1);
            s0 += __shfl_xor_sync(0xffffffffu, s0, 2);
            s1 += __shfl_xor_sync(0xffffffffu, s1, 1);
            s1 += __shfl_xor_sync(0xffffffffu, s1, 2);
            lrow[mf][0] += s0; lrow[mf][1] += s1;
        }

        // O += P V : V b-frags via ldmatrix.x4.trans, P from sf registers
#pragma unroll
        for (int kc = 0; kc < 4; kc++) {
            unsigned pa[2][4];
#pragma unroll
            for (int mf = 0; mf < 2; mf++) {
                pa[mf][0] = f2h2(sf[mf][2 * kc    ][0], sf[mf][2 * kc    ][1]);
                pa[mf][1] = f2h2(sf[mf][2 * kc    ][2], sf[mf][2 * kc    ][3]);
                pa[mf][2] = f2h2(sf[mf][2 * kc + 1][0], sf[mf][2 * kc + 1][1]);
                pa[mf][3] = f2h2(sf[mf][2 * kc + 1][2], sf[mf][2 * kc + 1][3]);
            }
#pragma unroll
            for (int u = 0; u < 2; u++) {
                // B frags (trans) for nf=2u, 2u+1
                int jrow = kc * 16 + ((ltile & 1) ? 8 : 0) + lrowi;
                int cu   = u * 8 + ((ltile >= 2) ? 4 : 0);
                unsigned vf[4];
                ldsm_x4_trans(vf, vs_base + (unsigned)((jrow * KS2 + cu) * 4));
#pragma unroll
                for (int mf = 0; mf < 2; mf++) {
                    mma_f16(oacc[mf][2 * u    ], pa[mf], &vf[0]);
                    mma_f16(oacc[mf][2 * u + 1], pa[mf], &vf[2]);
                }
            }
        }
    }

    // epilogue: normalize, gate, write g_wg
#pragma unroll
    for (int mf = 0; mf < 2; mf++) {
        float inv0 = 1.f / lrow[mf][0], inv1 = 1.f / lrow[mf][1];
        int r0 = qBase + m0 + mf * 16 + g, r1 = r0 + 8;
        const float* gate0 = g_gate + ((size_t)bh * NQ + r0) * CDIM;
        const float* gate1 = g_gate + ((size_t)bh * NQ + r1) * CDIM;
        float* w0 = g_wg + (((size_t)b * NQ + r0) * NH + h) * CDIM;
        float* w1 = g_wg + (((size_t)b * NQ + r1) * NH + h) * CDIM;
#pragma unroll
        for (int nf = 0; nf < 4; nf++) {
            int c = nf * 8 + 2 * tg;
            float2 ga = *(const float2*)(gate0 + c);
            float2 gb = *(const float2*)(gate1 + c);
            float2 oa, ob;
            oa.x = oacc[mf][nf][0] * inv0 * ga.x;
            oa.y = oacc[mf][nf][1] * inv0 * ga.y;
            ob.x = oacc[mf][nf][2] * inv1 * gb.x;
            ob.y = oacc[mf][nf][3] * inv1 * gb.y;
            *(float2*)(w0 + c) = oa;
            *(float2*)(w1 + c) = ob;
        }
    }
}

// Output projection: wg[49152,256] x output_w[256,256] + output_b. grid (4,384)
__global__ __launch_bounds__(256) void out_kernel(
    const float* __restrict__ output_b, float* __restrict__ out)
{
    const int rowBase = blockIdx.y * BM;
    const int n0 = blockIdx.x * BN;
    float acc[2][4][4];
    gemm_core_f16(g_wg, &g_wt[4][0][0], rowBase, n0, acc);

    const int t = threadIdx.x, lane = t & 31, wid = t >> 5;
    const int g = lane >> 2, tg = lane & 3;
    const int mBase = (wid & 3) * 32, nBase = (wid >> 2) * 32;
#pragma unroll
    for (int mf = 0; mf < 2; mf++)
#pragma unroll
        for (int nf = 0; nf < 4; nf++)
#pragma unroll
            for (int r = 0; r < 4; r++) {
                int row = rowBase + mBase + mf * 16 + ((r & 2) ? 8 : 0) + g;
                int n   = n0 + nBase + nf * 8 + tg * 2 + (r & 1);
                out[(size_t)row * ODIM + n] = acc[mf][nf][r] + output_b[n];
            }
}

extern "C" void kernel_launch(void* const* d_in, const int* in_sizes, int n_in,
                              void* d_out, int out_size)
{
    const float* q_data   = (const float*)d_in[0];
    const float* m_data   = (const float*)d_in[1];
    const float* bias     = (const float*)d_in[2];
    const float* nbias    = (const float*)d_in[3];
    const float* query_w  = (const float*)d_in[4];
    const float* key_w    = (const float*)d_in[5];
    const float* value_w  = (const float*)d_in[6];
    const float* gating_w = (const float*)d_in[7];
    const float* gating_b = (const float*)d_in[8];
    const float* output_w = (const float*)d_in[9];
    const float* output_b = (const float*)d_in[10];
    float* out = (float*)d_out;

    const int smem_attn = (TQ * QS2 + 2 * TJ * KS2) * 4 + TQ * BSTR * 4; // 55296 B
    cudaFuncSetAttribute(attn_mma_kernel, cudaFuncAttributeMaxDynamicSharedMemorySize, smem_attn);

    dim3 gpack(128, 5);
    pack_w_kernel<<<gpack, 256>>>(query_w, gating_w, key_w, value_w, output_w);

    dim3 gproj(8, MROWS / BM);
    proj_qg_kernel<<<gproj, 256>>>(q_data, gating_b);
    proj_kv_kernel<<<gproj, 256>>>(m_data);
    dim3 gattn(NQ / TQ, BDIM * NH);
    attn_mma_kernel<<<gattn, 128, smem_attn>>>(bias, nbias);
    dim3 gout(4, MROWS / BM);
    out_kernel<<<gout, 256>>>(output_b, out);
}